// round 3
// baseline (speedup 1.0000x reference)
#include <cuda_runtime.h>
#include <math.h>
#include <stdint.h>

// ---------------------------------------------------------------------------
// Problem constants
// ---------------------------------------------------------------------------
namespace {
constexpr int kD   = 1024;
constexpr int kH   = 16;
constexpr int kDH  = 64;
constexpr int kDC  = 256;
constexpr int kHID = 2048;
constexpr int kG   = 2;
constexpr int kEPG = 4;
constexpr int kE   = 8;
constexpr int kB   = 2;
constexpr int kT   = 2048;
constexpr int kS   = kB * kT;           // 4096 tokens
constexpr float kEPS = 1e-6f;
constexpr int kPadRows = kS * 2 + kE * 128;  // 9216 padded rows for grouped GEMM
constexpr int kMaxTiles = 80;                // >= sum ceil(cnt_e/128) <= 72
}

// ---------------------------------------------------------------------------
// Scratch (device globals — no runtime allocation allowed)
// ---------------------------------------------------------------------------
__device__ float g_q[kS * kD];
__device__ float g_k[kS * kD];
__device__ float g_v[kS * kD];
__device__ float g_kc[kS * kDC];
__device__ float g_vc[kS * kDC];
__device__ float g_attn[kS * kD];
__device__ float g_pre1[kS * kD];
__device__ float g_x[kS * kD];
__device__ float g_ff1[kS * 2 * kHID];
__device__ float g_mid[kS * kHID];
__device__ float g_sh[kS * kD];
__device__ float g_h[kS * kHID];
__device__ float g_contrib[(size_t)kPadRows * kD];
__device__ int   g_cnt[kE];
__device__ int   g_list[kE * kS];
__device__ float g_wts[kE * kS];
__device__ int   g_tokE[kS * 2];
__device__ int   g_tokSlot[kS * 2];
__device__ int   g_padoff[kE];
__device__ int   g_tileE[kMaxTiles];
__device__ int   g_tileRow0[kMaxTiles];
__device__ int   g_tileSlot0[kMaxTiles];
__device__ int   g_ntiles;

// ---------------------------------------------------------------------------
// Generic SGEMM: C[M,N] = A[M,K] @ B[K,N] (+ Add residual if EPI==1)
// 128x128 tile, BK=8, 8x8 per thread, double-buffered smem.
// Requires M%128==0, N%128==... (N%4==0 and grid covers tiles), K%8==0.
// ---------------------------------------------------------------------------
template <int EPI>
__global__ void __launch_bounds__(256) sgemm_kernel(
    const float* __restrict__ A, const float* __restrict__ B,
    float* __restrict__ C, const float* __restrict__ Add,
    int M, int N, int K)
{
    constexpr int TBM = 128, TBN = 128, TBK = 8, TTM = 8, TTN = 8;
    __shared__ float As[2][TBK][TBM];
    __shared__ float Bs[2][TBK][TBN];
    const int tid = threadIdx.x;
    const int bm = blockIdx.y * TBM;
    const int bn = blockIdx.x * TBN;
    const int arow = tid >> 1;
    const int acol = (tid & 1) << 2;
    const int brow = tid >> 5;
    const int bcol = (tid & 31) << 2;
    const int tx = tid & 15;
    const int ty = tid >> 4;
    const float* Ap = A + (size_t)(bm + arow) * K + acol;
    const float* Bp = B + (size_t)brow * N + bn + bcol;

    float acc[TTM][TTN];
#pragma unroll
    for (int i = 0; i < TTM; i++)
#pragma unroll
        for (int j = 0; j < TTN; j++) acc[i][j] = 0.f;

    float4 pa = *(const float4*)Ap;
    float4 pb = *(const float4*)Bp;
    As[0][acol + 0][arow] = pa.x;
    As[0][acol + 1][arow] = pa.y;
    As[0][acol + 2][arow] = pa.z;
    As[0][acol + 3][arow] = pa.w;
    *(float4*)&Bs[0][brow][bcol] = pb;
    __syncthreads();

    const int nk = K / TBK;
    int buf = 0;
    for (int kt = 0; kt < nk; kt++) {
        if (kt + 1 < nk) {
            pa = *(const float4*)(Ap + (kt + 1) * TBK);
            pb = *(const float4*)(Bp + (size_t)(kt + 1) * TBK * N);
        }
#pragma unroll
        for (int k = 0; k < TBK; k++) {
            float ra[TTM], rb[TTN];
            *(float4*)&ra[0] = *(const float4*)&As[buf][k][ty * TTM];
            *(float4*)&ra[4] = *(const float4*)&As[buf][k][ty * TTM + 4];
            *(float4*)&rb[0] = *(const float4*)&Bs[buf][k][tx * TTN];
            *(float4*)&rb[4] = *(const float4*)&Bs[buf][k][tx * TTN + 4];
#pragma unroll
            for (int i = 0; i < TTM; i++)
#pragma unroll
                for (int j = 0; j < TTN; j++)
                    acc[i][j] = fmaf(ra[i], rb[j], acc[i][j]);
        }
        if (kt + 1 < nk) {
            const int nb = buf ^ 1;
            As[nb][acol + 0][arow] = pa.x;
            As[nb][acol + 1][arow] = pa.y;
            As[nb][acol + 2][arow] = pa.z;
            As[nb][acol + 3][arow] = pa.w;
            *(float4*)&Bs[nb][brow][bcol] = pb;
            __syncthreads();
            buf = nb;
        }
    }
#pragma unroll
    for (int i = 0; i < TTM; i++) {
        const size_t row = (size_t)(bm + ty * TTM + i);
        float* cp = C + row * N + bn + tx * TTN;
#pragma unroll
        for (int j = 0; j < TTN; j += 4) {
            float4 r = make_float4(acc[i][j], acc[i][j + 1], acc[i][j + 2], acc[i][j + 3]);
            if (EPI == 1) {
                float4 a = *(const float4*)(Add + row * N + bn + tx * TTN + j);
                r.x += a.x; r.y += a.y; r.z += a.z; r.w += a.w;
            }
            *(float4*)(cp + j) = r;
        }
    }
}

// ---------------------------------------------------------------------------
// Grouped MoE GEMM: contrib[perm_rows, D] = (w * h[tok]) @ W2[expert]
// Row tiles mapped per-expert via tile table; padding rows -> zero.
// ---------------------------------------------------------------------------
__global__ void __launch_bounds__(256) moe_gemm_kernel(
    const float* __restrict__ Hm, const float* __restrict__ W2)
{
    constexpr int TBM = 128, TBN = 128, TBK = 8, TTM = 8, TTN = 8;
    __shared__ float As[2][TBK][TBM];
    __shared__ float Bs[2][TBK][TBN];
    const int t = blockIdx.y;
    if (t >= g_ntiles) return;
    const int e = g_tileE[t];
    const int row0 = g_tileRow0[t];
    const int slot0 = g_tileSlot0[t];
    const int cnt = g_cnt[e];
    const float* B = W2 + (size_t)e * kHID * kD;

    const int tid = threadIdx.x;
    const int bn = blockIdx.x * TBN;
    const int arow = tid >> 1;
    const int acol = (tid & 1) << 2;
    const int brow = tid >> 5;
    const int bcol = (tid & 31) << 2;
    const int tx = tid & 15;
    const int ty = tid >> 4;

    const int slot = slot0 + arow;
    const bool valid = slot < cnt;
    const int tok = valid ? g_list[e * kS + slot] : 0;
    const float wt = valid ? g_wts[e * kS + slot] : 0.f;
    const float* Ap = Hm + (size_t)tok * kHID + acol;
    const float* Bp = B + (size_t)brow * kD + bn + bcol;

    float acc[TTM][TTN];
#pragma unroll
    for (int i = 0; i < TTM; i++)
#pragma unroll
        for (int j = 0; j < TTN; j++) acc[i][j] = 0.f;

    float4 pa = *(const float4*)Ap;
    float4 pb = *(const float4*)Bp;
    As[0][acol + 0][arow] = pa.x * wt;
    As[0][acol + 1][arow] = pa.y * wt;
    As[0][acol + 2][arow] = pa.z * wt;
    As[0][acol + 3][arow] = pa.w * wt;
    *(float4*)&Bs[0][brow][bcol] = pb;
    __syncthreads();

    const int nk = kHID / TBK;
    int buf = 0;
    for (int kt = 0; kt < nk; kt++) {
        if (kt + 1 < nk) {
            pa = *(const float4*)(Ap + (kt + 1) * TBK);
            pb = *(const float4*)(Bp + (size_t)(kt + 1) * TBK * kD);
        }
#pragma unroll
        for (int k = 0; k < TBK; k++) {
            float ra[TTM], rb[TTN];
            *(float4*)&ra[0] = *(const float4*)&As[buf][k][ty * TTM];
            *(float4*)&ra[4] = *(const float4*)&As[buf][k][ty * TTM + 4];
            *(float4*)&rb[0] = *(const float4*)&Bs[buf][k][tx * TTN];
            *(float4*)&rb[4] = *(const float4*)&Bs[buf][k][tx * TTN + 4];
#pragma unroll
            for (int i = 0; i < TTM; i++)
#pragma unroll
                for (int j = 0; j < TTN; j++)
                    acc[i][j] = fmaf(ra[i], rb[j], acc[i][j]);
        }
        if (kt + 1 < nk) {
            const int nb = buf ^ 1;
            As[nb][acol + 0][arow] = pa.x * wt;
            As[nb][acol + 1][arow] = pa.y * wt;
            As[nb][acol + 2][arow] = pa.z * wt;
            As[nb][acol + 3][arow] = pa.w * wt;
            *(float4*)&Bs[nb][brow][bcol] = pb;
            __syncthreads();
            buf = nb;
        }
    }
#pragma unroll
    for (int i = 0; i < TTM; i++) {
        const size_t row = (size_t)(row0 + ty * TTM + i);
        float* cp = g_contrib + row * kD + bn + tx * TTN;
#pragma unroll
        for (int j = 0; j < TTN; j += 4) {
            float4 r = make_float4(acc[i][j], acc[i][j + 1], acc[i][j + 2], acc[i][j + 3]);
            *(float4*)(cp + j) = r;
        }
    }
}

// ---------------------------------------------------------------------------
// RoPE (interleaved pairs) applied in-place to q and k.
// grid = S, block = 512 (16 heads x 32 pairs)
// ---------------------------------------------------------------------------
__global__ void __launch_bounds__(512) rope_kernel(float* __restrict__ q, float* __restrict__ k)
{
    const int s = blockIdx.x;
    const int j = threadIdx.x;
    const int h = j >> 5;
    const int i = j & 31;
    const int t = s & (kT - 1);  // s % T
    const float inv = (float)exp(-((double)(2 * i) / (double)kDH) * 9.210340371976182736);
    const float ang = (float)t * inv;
    float sn, cs;
    sincosf(ang, &sn, &cs);
    const size_t base = (size_t)s * kD + h * kDH + 2 * i;
    float q1 = q[base], q2 = q[base + 1];
    q[base]     = q1 * cs - q2 * sn;
    q[base + 1] = q1 * sn + q2 * cs;
    float k1 = k[base], k2 = k[base + 1];
    k[base]     = k1 * cs - k2 * sn;
    k[base + 1] = k1 * sn + k2 * cs;
}

// ---------------------------------------------------------------------------
// Flash attention, fp32, 64-query tiles, DH=64, non-causal.
// grid (T/64, H, B), 256 threads. 48KB static smem (Qs + K/P union + Vs).
// ---------------------------------------------------------------------------
__global__ void __launch_bounds__(256) flash_kernel(
    const float* __restrict__ q, const float* __restrict__ k,
    const float* __restrict__ v, float* __restrict__ o)
{
    __shared__ float Qs[64][64];   // [d][row], pre-scaled
    __shared__ float KP[64][64];   // K as [d][col]; reused as P[kcol][qrow]
    __shared__ float Vs[64][64];   // [k][d]
    const int qt = blockIdx.x, hh = blockIdx.y, bb = blockIdx.z;
    const int tid = threadIdx.x;
    const int tx = tid & 15, ty = tid >> 4;
    const int lr = tid >> 2;           // 0..63
    const int lc = (tid & 3) * 16;     // 0,16,32,48
    const float scale = 0.125f;        // 1/sqrt(64)

    {
        const float* qp = q + ((size_t)(bb * kT + qt * 64 + lr) * kH + hh) * kDH + lc;
#pragma unroll
        for (int c = 0; c < 4; c++) {
            float4 t4 = *(const float4*)(qp + c * 4);
            Qs[lc + c * 4 + 0][lr] = t4.x * scale;
            Qs[lc + c * 4 + 1][lr] = t4.y * scale;
            Qs[lc + c * 4 + 2][lr] = t4.z * scale;
            Qs[lc + c * 4 + 3][lr] = t4.w * scale;
        }
    }
    float m_i[4], l_i[4], O[4][4];
#pragma unroll
    for (int i = 0; i < 4; i++) {
        m_i[i] = -1e30f; l_i[i] = 0.f;
#pragma unroll
        for (int j = 0; j < 4; j++) O[i][j] = 0.f;
    }

    for (int jt = 0; jt < kT / 64; jt++) {
        __syncthreads();  // previous PV reads + Qs visibility
        {
            const float* kp = k + ((size_t)(bb * kT + jt * 64 + lr) * kH + hh) * kDH + lc;
            const float* vp = v + ((size_t)(bb * kT + jt * 64 + lr) * kH + hh) * kDH + lc;
#pragma unroll
            for (int c = 0; c < 4; c++) {
                float4 t4 = *(const float4*)(kp + c * 4);
                KP[lc + c * 4 + 0][lr] = t4.x;
                KP[lc + c * 4 + 1][lr] = t4.y;
                KP[lc + c * 4 + 2][lr] = t4.z;
                KP[lc + c * 4 + 3][lr] = t4.w;
                float4 v4 = *(const float4*)(vp + c * 4);
                *(float4*)&Vs[lr][lc + c * 4] = v4;
            }
        }
        __syncthreads();
        float s[4][4];
#pragma unroll
        for (int i = 0; i < 4; i++)
#pragma unroll
            for (int j = 0; j < 4; j++) s[i][j] = 0.f;
#pragma unroll 8
        for (int d = 0; d < 64; d++) {
            float qa[4], kb[4];
            *(float4*)qa = *(const float4*)&Qs[d][ty * 4];
            *(float4*)kb = *(const float4*)&KP[d][tx * 4];
#pragma unroll
            for (int i = 0; i < 4; i++)
#pragma unroll
                for (int j = 0; j < 4; j++) s[i][j] = fmaf(qa[i], kb[j], s[i][j]);
        }
        // online softmax stats (16 lanes per query row share via shfl width 16)
#pragma unroll
        for (int i = 0; i < 4; i++) {
            float mx = fmaxf(fmaxf(s[i][0], s[i][1]), fmaxf(s[i][2], s[i][3]));
            mx = fmaxf(mx, __shfl_xor_sync(0xffffffffu, mx, 1, 16));
            mx = fmaxf(mx, __shfl_xor_sync(0xffffffffu, mx, 2, 16));
            mx = fmaxf(mx, __shfl_xor_sync(0xffffffffu, mx, 4, 16));
            mx = fmaxf(mx, __shfl_xor_sync(0xffffffffu, mx, 8, 16));
            const float mnew = fmaxf(m_i[i], mx);
            const float corr = __expf(m_i[i] - mnew);
            float r = 0.f;
#pragma unroll
            for (int j = 0; j < 4; j++) {
                const float p = __expf(s[i][j] - mnew);
                s[i][j] = p; r += p;
            }
            r += __shfl_xor_sync(0xffffffffu, r, 1, 16);
            r += __shfl_xor_sync(0xffffffffu, r, 2, 16);
            r += __shfl_xor_sync(0xffffffffu, r, 4, 16);
            r += __shfl_xor_sync(0xffffffffu, r, 8, 16);
            l_i[i] = l_i[i] * corr + r;
            m_i[i] = mnew;
#pragma unroll
            for (int j = 0; j < 4; j++) O[i][j] *= corr;
        }
        __syncthreads();  // all S reads of KP done before P overwrite
#pragma unroll
        for (int i = 0; i < 4; i++)
#pragma unroll
            for (int j = 0; j < 4; j++) KP[tx * 4 + j][ty * 4 + i] = s[i][j];
        __syncthreads();
#pragma unroll 8
        for (int kk = 0; kk < 64; kk++) {
            float pr[4], vr[4];
            *(float4*)pr = *(const float4*)&KP[kk][ty * 4];
            *(float4*)vr = *(const float4*)&Vs[kk][tx * 4];
#pragma unroll
            for (int i = 0; i < 4; i++)
#pragma unroll
                for (int j = 0; j < 4; j++) O[i][j] = fmaf(pr[i], vr[j], O[i][j]);
        }
    }
#pragma unroll
    for (int i = 0; i < 4; i++) {
        const float invl = 1.f / l_i[i];
        const int row = qt * 64 + ty * 4 + i;
        float* op = o + ((size_t)(bb * kT + row) * kH + hh) * kDH + tx * 4;
        *(float4*)op = make_float4(O[i][0] * invl, O[i][1] * invl, O[i][2] * invl, O[i][3] * invl);
    }
}

// ---------------------------------------------------------------------------
// RMSNorm: one block (256 thr) per token, in -> out with weight w.
// ---------------------------------------------------------------------------
__global__ void __launch_bounds__(256) rmsnorm_kernel(
    const float* __restrict__ in, const float* __restrict__ w, float* __restrict__ out)
{
    __shared__ float red[8];
    const int s = blockIdx.x;
    const int tid = threadIdx.x;
    const float* row = in + (size_t)s * kD;
    float4 v = *(const float4*)(row + tid * 4);
    float ss = v.x * v.x + v.y * v.y + v.z * v.z + v.w * v.w;
#pragma unroll
    for (int o = 16; o; o >>= 1) ss += __shfl_xor_sync(0xffffffffu, ss, o);
    if ((tid & 31) == 0) red[tid >> 5] = ss;
    __syncthreads();
    if (tid < 32) {
        float r = (tid < 8) ? red[tid] : 0.f;
#pragma unroll
        for (int o = 4; o; o >>= 1) r += __shfl_xor_sync(0xffffffffu, r, o);
        if (tid == 0) red[0] = r;
    }
    __syncthreads();
    const float sc = rsqrtf(red[0] * (1.f / (float)kD) + kEPS);
    float4 wv = *(const float4*)(w + tid * 4);
    *(float4*)(out + (size_t)s * kD + tid * 4) =
        make_float4(v.x * sc * wv.x, v.y * sc * wv.y, v.z * sc * wv.z, v.w * sc * wv.w);
}

// ---------------------------------------------------------------------------
// SwiGLU: out[s, j] = silu(in[s, j]) * in[s, HID + j]
// ---------------------------------------------------------------------------
__global__ void __launch_bounds__(256) swiglu_kernel(
    const float* __restrict__ in, float* __restrict__ out)
{
    const int idx = blockIdx.x * blockDim.x + threadIdx.x;  // over S*HID
    const int s = idx / kHID;
    const int j = idx - s * kHID;
    const float a = in[(size_t)s * 2 * kHID + j];
    const float b = in[(size_t)s * 2 * kHID + kHID + j];
    const float sig = 1.f / (1.f + expf(-a));
    out[idx] = a * sig * b;
}

// ---------------------------------------------------------------------------
// Gating: 1 warp per token. Computes group softmax/argmax, in-group expert
// softmax, top-2, and records (expert, slot) assignments via atomics.
// ---------------------------------------------------------------------------
__global__ void __launch_bounds__(128) gate_kernel(
    const float* __restrict__ x, const float* __restrict__ Wg,
    const float* __restrict__ We, const float* __restrict__ gb,
    const float* __restrict__ eb)
{
    const int s = blockIdx.x * 4 + (threadIdx.x >> 5);
    const int lane = threadIdx.x & 31;
    const float* row = x + (size_t)s * kD;
    float ag0 = 0.f, ag1 = 0.f;
    float ae[kE] = {};
    for (int d = lane; d < kD; d += 32) {
        const float xv = row[d];
        ag0 = fmaf(xv, Wg[d * 2 + 0], ag0);
        ag1 = fmaf(xv, Wg[d * 2 + 1], ag1);
#pragma unroll
        for (int e = 0; e < kE; e++) ae[e] = fmaf(xv, We[d * 8 + e], ae[e]);
    }
#pragma unroll
    for (int o = 16; o; o >>= 1) {
        ag0 += __shfl_xor_sync(0xffffffffu, ag0, o);
        ag1 += __shfl_xor_sync(0xffffffffu, ag1, o);
#pragma unroll
        for (int e = 0; e < kE; e++) ae[e] += __shfl_xor_sync(0xffffffffu, ae[e], o);
    }
    if (lane == 0) {
        const float gl0 = ag0 + gb[0], gl1 = ag1 + gb[1];
        const int gi = (gl1 > gl0) ? 1 : 0;  // first-max tie-break like jnp.argmax
        const float gprob = 1.f / (1.f + expf(gi ? (gl0 - gl1) : (gl1 - gl0)));
        const int base = gi * kEPG;
        float el[kEPG];
#pragma unroll
        for (int j = 0; j < kEPG; j++) el[j] = ae[base + j] + eb[base + j];
        float mx = el[0];
#pragma unroll
        for (int j = 1; j < kEPG; j++) mx = fmaxf(mx, el[j]);
        float ex[kEPG], ssum = 0.f;
#pragma unroll
        for (int j = 0; j < kEPG; j++) { ex[j] = expf(el[j] - mx); ssum += ex[j]; }
        float p[kEPG];
        const float inv = gprob / ssum;
#pragma unroll
        for (int j = 0; j < kEPG; j++) p[j] = ex[j] * inv;
        int i1 = 0;
#pragma unroll
        for (int j = 1; j < kEPG; j++) if (p[j] > p[i1]) i1 = j;
        int i2 = (i1 == 0) ? 1 : 0;
#pragma unroll
        for (int j = 0; j < kEPG; j++) if (j != i1 && p[j] > p[i2]) i2 = j;

        int ee = base + i1;
        int sl = atomicAdd(&g_cnt[ee], 1);
        g_list[ee * kS + sl] = s; g_wts[ee * kS + sl] = p[i1];
        g_tokE[s * 2 + 0] = ee; g_tokSlot[s * 2 + 0] = sl;
        ee = base + i2;
        sl = atomicAdd(&g_cnt[ee], 1);
        g_list[ee * kS + sl] = s; g_wts[ee * kS + sl] = p[i2];
        g_tokE[s * 2 + 1] = ee; g_tokSlot[s * 2 + 1] = sl;
    }
}

__global__ void zero_cnt_kernel()
{
    if (threadIdx.x < kE) g_cnt[threadIdx.x] = 0;
}

// Build padded segment offsets + tile table (serial, trivial work).
__global__ void offsets_kernel()
{
    if (threadIdx.x == 0 && blockIdx.x == 0) {
        int off = 0, nt = 0;
        for (int e = 0; e < kE; e++) {
            g_padoff[e] = off;
            const int c = g_cnt[e];
            const int tiles = (c + 127) >> 7;
            for (int i = 0; i < tiles; i++) {
                g_tileE[nt] = e;
                g_tileRow0[nt] = off + i * 128;
                g_tileSlot0[nt] = i * 128;
                nt++;
            }
            off += tiles * 128;
        }
        g_ntiles = nt;
    }
}

// ---------------------------------------------------------------------------
// Final: out = rmsnorm(x + shared + contrib[pos0] + contrib[pos1], norm2_w)
// ---------------------------------------------------------------------------
__global__ void __launch_bounds__(256) final_kernel(
    const float* __restrict__ x, const float* __restrict__ sh,
    const float* __restrict__ w2, float* __restrict__ out)
{
    __shared__ float red[8];
    const int s = blockIdx.x;
    const int tid = threadIdx.x;
    const int e0 = g_tokE[s * 2 + 0], sl0 = g_tokSlot[s * 2 + 0];
    const int e1 = g_tokE[s * 2 + 1], sl1 = g_tokSlot[s * 2 + 1];
    const float* c0 = g_contrib + (size_t)(g_padoff[e0] + sl0) * kD;
    const float* c1 = g_contrib + (size_t)(g_padoff[e1] + sl1) * kD;
    const int j = tid * 4;
    float4 a = *(const float4*)(x + (size_t)s * kD + j);
    float4 b = *(const float4*)(sh + (size_t)s * kD + j);
    float4 p = *(const float4*)(c0 + j);
    float4 q = *(const float4*)(c1 + j);
    float4 v = make_float4(a.x + b.x + p.x + q.x, a.y + b.y + p.y + q.y,
                           a.z + b.z + p.z + q.z, a.w + b.w + p.w + q.w);
    float ss = v.x * v.x + v.y * v.y + v.z * v.z + v.w * v.w;
#pragma unroll
    for (int o = 16; o; o >>= 1) ss += __shfl_xor_sync(0xffffffffu, ss, o);
    if ((tid & 31) == 0) red[tid >> 5] = ss;
    __syncthreads();
    if (tid < 32) {
        float r = (tid < 8) ? red[tid] : 0.f;
#pragma unroll
        for (int o = 4; o; o >>= 1) r += __shfl_xor_sync(0xffffffffu, r, o);
        if (tid == 0) red[0] = r;
    }
    __syncthreads();
    const float sc = rsqrtf(red[0] * (1.f / (float)kD) + kEPS);
    float4 wv = *(const float4*)(w2 + j);
    *(float4*)(out + (size_t)s * kD + j) =
        make_float4(v.x * sc * wv.x, v.y * sc * wv.y, v.z * sc * wv.z, v.w * sc * wv.w);
}

// ---------------------------------------------------------------------------
// Launch
// ---------------------------------------------------------------------------
extern "C" void kernel_launch(void* const* d_in, const int* in_sizes, int n_in,
                              void* d_out, int out_size)
{
    (void)in_sizes; (void)n_in; (void)out_size;
    const float* src  = (const float*)d_in[0];
    const float* Wq   = (const float*)d_in[1];
    const float* Wk_c = (const float*)d_in[2];
    const float* Wv_c = (const float*)d_in[3];
    const float* Wk   = (const float*)d_in[4];
    const float* Wv   = (const float*)d_in[5];
    const float* Wo   = (const float*)d_in[6];
    const float* Wsi  = (const float*)d_in[7];
    const float* Wso  = (const float*)d_in[8];
    const float* W1s  = (const float*)d_in[9];
    const float* W2e  = (const float*)d_in[10];
    const float* Wgg  = (const float*)d_in[11];
    const float* Weg  = (const float*)d_in[12];
    const float* gbia = (const float*)d_in[13];
    const float* ebia = (const float*)d_in[14];
    const float* n1w  = (const float*)d_in[15];
    const float* n2w  = (const float*)d_in[16];
    float* out = (float*)d_out;

    float *q, *k, *v, *kc, *vc, *attn, *pre1, *x, *ff1, *mid, *sh, *h;
    cudaGetSymbolAddress((void**)&q, g_q);
    cudaGetSymbolAddress((void**)&k, g_k);
    cudaGetSymbolAddress((void**)&v, g_v);
    cudaGetSymbolAddress((void**)&kc, g_kc);
    cudaGetSymbolAddress((void**)&vc, g_vc);
    cudaGetSymbolAddress((void**)&attn, g_attn);
    cudaGetSymbolAddress((void**)&pre1, g_pre1);
    cudaGetSymbolAddress((void**)&x, g_x);
    cudaGetSymbolAddress((void**)&ff1, g_ff1);
    cudaGetSymbolAddress((void**)&mid, g_mid);
    cudaGetSymbolAddress((void**)&sh, g_sh);
    cudaGetSymbolAddress((void**)&h, g_h);

    const dim3 gDD(kD / 128, kS / 128);             // (8, 32)
    const dim3 gDC(kDC / 128, kS / 128);            // (2, 32)
    const dim3 gFF(2 * kHID / 128, kS / 128);       // (32, 32)

    // Attention projections (low-rank k/v)
    sgemm_kernel<0><<<gDD, 256>>>(src, Wq, q, nullptr, kS, kD, kD);
    sgemm_kernel<0><<<gDC, 256>>>(src, Wk_c, kc, nullptr, kS, kDC, kD);
    sgemm_kernel<0><<<gDC, 256>>>(src, Wv_c, vc, nullptr, kS, kDC, kD);
    sgemm_kernel<0><<<gDD, 256>>>(kc, Wk, k, nullptr, kS, kD, kDC);
    sgemm_kernel<0><<<gDD, 256>>>(vc, Wv, v, nullptr, kS, kD, kDC);

    rope_kernel<<<kS, 512>>>(q, k);
    flash_kernel<<<dim3(kT / 64, kH, kB), 256>>>(q, k, v, attn);

    // Output projection + residual, then rmsnorm
    sgemm_kernel<1><<<gDD, 256>>>(attn, Wo, pre1, src, kS, kD, kD);
    rmsnorm_kernel<<<kS, 256>>>(pre1, n1w, x);

    // Shared FFN
    sgemm_kernel<0><<<gFF, 256>>>(x, Wsi, ff1, nullptr, kS, 2 * kHID, kD);
    swiglu_kernel<<<(kS * kHID) / 256, 256>>>(ff1, mid);
    sgemm_kernel<0><<<gDD, 256>>>(mid, Wso, sh, nullptr, kS, kD, kHID);

    // Shared expert hidden h (reuse ff1 buffer)
    sgemm_kernel<0><<<gFF, 256>>>(x, W1s, ff1, nullptr, kS, 2 * kHID, kD);
    swiglu_kernel<<<(kS * kHID) / 256, 256>>>(ff1, h);

    // Gating + grouped routed GEMM
    zero_cnt_kernel<<<1, 32>>>();
    gate_kernel<<<kS / 4, 128>>>(x, Wgg, Weg, gbia, ebia);
    offsets_kernel<<<1, 32>>>();
    moe_gemm_kernel<<<dim3(kD / 128, 72), 256>>>(h, W2e);

    // Final combine + rmsnorm
    final_kernel<<<kS, 256>>>(x, sh, n2w, out);
}

// round 4
// speedup vs baseline: 1.1545x; 1.1545x over previous
#include <cuda_runtime.h>
#include <math.h>
#include <stdint.h>

// ---------------------------------------------------------------------------
// Problem constants
// ---------------------------------------------------------------------------
namespace {
constexpr int kD   = 1024;
constexpr int kH   = 16;
constexpr int kDH  = 64;
constexpr int kDC  = 256;
constexpr int kHID = 2048;
constexpr int kG   = 2;
constexpr int kEPG = 4;
constexpr int kE   = 8;
constexpr int kB   = 2;
constexpr int kT   = 2048;
constexpr int kS   = kB * kT;           // 4096 tokens
constexpr float kEPS = 1e-6f;
constexpr int kPadRows = kS * 2 + kE * 128;  // 9216 padded rows for grouped GEMM
constexpr int kMaxTiles = 80;
}

// ---------------------------------------------------------------------------
// Scratch (device globals — no runtime allocation allowed)
// ---------------------------------------------------------------------------
__device__ float g_q[kS * kD];
__device__ float g_k[kS * kD];
__device__ float g_v[kS * kD];
__device__ float g_kc[kS * kDC];
__device__ float g_vc[kS * kDC];
__device__ float g_attn[kS * kD];
__device__ float g_pre1[kS * kD];
__device__ float g_x[kS * kD];
__device__ float g_ff1[kS * 2 * kHID];
__device__ float g_mid[kS * kHID];
__device__ float g_sh[kS * kD];
__device__ float g_h[kS * kHID];
__device__ float g_contrib[(size_t)kPadRows * kD];
__device__ int   g_cnt[kE];
__device__ int   g_list[kE * kS];
__device__ float g_wts[kE * kS];
__device__ int   g_tokE[kS * 2];
__device__ int   g_tokSlot[kS * 2];
__device__ int   g_padoff[kE];
__device__ int   g_tileE[kMaxTiles];
__device__ int   g_tileRow0[kMaxTiles];
__device__ int   g_tileSlot0[kMaxTiles];
__device__ int   g_ntiles;

// ---------------------------------------------------------------------------
// tf32 helpers
// ---------------------------------------------------------------------------
__device__ __forceinline__ uint32_t f2tf32(float v) {
    uint32_t u;
    asm("cvt.rna.tf32.f32 %0, %1;" : "=r"(u) : "f"(v));
    return u;
}

__device__ __forceinline__ void mma_tf32(float* c, const uint32_t* a, const uint32_t* b) {
    asm("mma.sync.aligned.m16n8k8.row.col.f32.tf32.tf32.f32 "
        "{%0,%1,%2,%3}, {%4,%5,%6,%7}, {%8,%9}, {%0,%1,%2,%3};\n"
        : "+f"(c[0]), "+f"(c[1]), "+f"(c[2]), "+f"(c[3])
        : "r"(a[0]), "r"(a[1]), "r"(a[2]), "r"(a[3]), "r"(b[0]), "r"(b[1]));
}

// ---------------------------------------------------------------------------
// tf32 tensor-core GEMM: C[M,N] = A[M,K] @ B[K,N] (+ Add if EPI==1)
// 128x128 block tile, BK=16, 256 threads, 8 warps of 64x32.
// Requires M%128==0, N%128==0, K%16==0.
// smem pitch 136 (pad 8) -> conflict-free fragment LDS.
// ---------------------------------------------------------------------------
template <int EPI>
__global__ void __launch_bounds__(256) tgemm_kernel(
    const float* __restrict__ A, const float* __restrict__ B,
    float* __restrict__ C, const float* __restrict__ Add,
    int M, int N, int K)
{
    constexpr int PITCH = 136;
    __shared__ uint32_t As[2][16][PITCH];
    __shared__ uint32_t Bs[2][16][PITCH];

    const int tid = threadIdx.x;
    const int warp = tid >> 5;
    const int lane = tid & 31;
    const int gid = lane >> 2;
    const int tig = lane & 3;
    const int wm = (warp >> 2) * 64;   // 2 warp rows
    const int wn = (warp & 3) * 32;    // 4 warp cols
    const int bm = blockIdx.y * 128;
    const int bn = blockIdx.x * 128;

    // A loader: thread covers row ar, cols ac..ac+7
    const int ar = tid >> 1;
    const int ac = (tid & 1) * 8;
    const float* Ap = A + (size_t)(bm + ar) * K + ac;
    // B loader: two rows bk0 and bk0+8, 4 cols starting bn4
    const int bk0 = tid >> 5;
    const int bn4 = (lane) * 4;
    const float* Bp = B + (size_t)bk0 * N + bn + bn4;

    float acc[4][4][4];
#pragma unroll
    for (int mt = 0; mt < 4; mt++)
#pragma unroll
        for (int nt = 0; nt < 4; nt++)
#pragma unroll
            for (int i = 0; i < 4; i++) acc[mt][nt][i] = 0.f;

    // stage 0 load
    {
        float4 pa0 = *(const float4*)Ap;
        float4 pa1 = *(const float4*)(Ap + 4);
        float4 pb0 = *(const float4*)Bp;
        float4 pb1 = *(const float4*)(Bp + (size_t)8 * N);
        As[0][ac + 0][ar] = f2tf32(pa0.x); As[0][ac + 1][ar] = f2tf32(pa0.y);
        As[0][ac + 2][ar] = f2tf32(pa0.z); As[0][ac + 3][ar] = f2tf32(pa0.w);
        As[0][ac + 4][ar] = f2tf32(pa1.x); As[0][ac + 5][ar] = f2tf32(pa1.y);
        As[0][ac + 6][ar] = f2tf32(pa1.z); As[0][ac + 7][ar] = f2tf32(pa1.w);
        *(uint4*)&Bs[0][bk0][bn4] =
            make_uint4(f2tf32(pb0.x), f2tf32(pb0.y), f2tf32(pb0.z), f2tf32(pb0.w));
        *(uint4*)&Bs[0][bk0 + 8][bn4] =
            make_uint4(f2tf32(pb1.x), f2tf32(pb1.y), f2tf32(pb1.z), f2tf32(pb1.w));
    }
    __syncthreads();

    const int nk = K / 16;
    int buf = 0;
    for (int kt = 0; kt < nk; kt++) {
        float4 pa0, pa1, pb0, pb1;
        if (kt + 1 < nk) {
            pa0 = *(const float4*)(Ap + (kt + 1) * 16);
            pa1 = *(const float4*)(Ap + (kt + 1) * 16 + 4);
            pb0 = *(const float4*)(Bp + (size_t)(kt + 1) * 16 * N);
            pb1 = *(const float4*)(Bp + (size_t)((kt + 1) * 16 + 8) * N);
        }
#pragma unroll
        for (int ks = 0; ks < 2; ks++) {
            const int k0 = ks * 8;
            uint32_t af[4][4], bf[4][2];
#pragma unroll
            for (int mt = 0; mt < 4; mt++) {
                const int row = wm + mt * 16 + gid;
                af[mt][0] = As[buf][k0 + tig][row];
                af[mt][1] = As[buf][k0 + tig][row + 8];
                af[mt][2] = As[buf][k0 + tig + 4][row];
                af[mt][3] = As[buf][k0 + tig + 4][row + 8];
            }
#pragma unroll
            for (int nt = 0; nt < 4; nt++) {
                const int col = wn + nt * 8 + gid;
                bf[nt][0] = Bs[buf][k0 + tig][col];
                bf[nt][1] = Bs[buf][k0 + tig + 4][col];
            }
#pragma unroll
            for (int mt = 0; mt < 4; mt++)
#pragma unroll
                for (int nt = 0; nt < 4; nt++)
                    mma_tf32(acc[mt][nt], af[mt], bf[nt]);
        }
        if (kt + 1 < nk) {
            const int nb = buf ^ 1;
            As[nb][ac + 0][ar] = f2tf32(pa0.x); As[nb][ac + 1][ar] = f2tf32(pa0.y);
            As[nb][ac + 2][ar] = f2tf32(pa0.z); As[nb][ac + 3][ar] = f2tf32(pa0.w);
            As[nb][ac + 4][ar] = f2tf32(pa1.x); As[nb][ac + 5][ar] = f2tf32(pa1.y);
            As[nb][ac + 6][ar] = f2tf32(pa1.z); As[nb][ac + 7][ar] = f2tf32(pa1.w);
            *(uint4*)&Bs[nb][bk0][bn4] =
                make_uint4(f2tf32(pb0.x), f2tf32(pb0.y), f2tf32(pb0.z), f2tf32(pb0.w));
            *(uint4*)&Bs[nb][bk0 + 8][bn4] =
                make_uint4(f2tf32(pb1.x), f2tf32(pb1.y), f2tf32(pb1.z), f2tf32(pb1.w));
            __syncthreads();
            buf = nb;
        }
    }

    // epilogue
#pragma unroll
    for (int mt = 0; mt < 4; mt++) {
        const int row = bm + wm + mt * 16 + gid;
#pragma unroll
        for (int nt = 0; nt < 4; nt++) {
            const int col = bn + wn + nt * 8 + 2 * tig;
            float2 r0 = make_float2(acc[mt][nt][0], acc[mt][nt][1]);
            float2 r1 = make_float2(acc[mt][nt][2], acc[mt][nt][3]);
            if (EPI == 1) {
                float2 a0 = *(const float2*)(Add + (size_t)row * N + col);
                float2 a1 = *(const float2*)(Add + (size_t)(row + 8) * N + col);
                r0.x += a0.x; r0.y += a0.y; r1.x += a1.x; r1.y += a1.y;
            }
            *(float2*)(C + (size_t)row * N + col) = r0;
            *(float2*)(C + (size_t)(row + 8) * N + col) = r1;
        }
    }
}

// ---------------------------------------------------------------------------
// Grouped MoE GEMM (tf32): contrib[perm_rows, D] = (w * h[tok]) @ W2[expert]
// Same structure as tgemm; A rows gathered via g_list, scaled by g_wts.
// ---------------------------------------------------------------------------
__global__ void __launch_bounds__(256) moe_gemm_kernel(
    const float* __restrict__ Hm, const float* __restrict__ W2)
{
    constexpr int PITCH = 136;
    __shared__ uint32_t As[2][16][PITCH];
    __shared__ uint32_t Bs[2][16][PITCH];

    const int t = blockIdx.y;
    if (t >= g_ntiles) return;
    const int e = g_tileE[t];
    const int row0 = g_tileRow0[t];
    const int slot0 = g_tileSlot0[t];
    const int cnt = g_cnt[e];
    const float* B = W2 + (size_t)e * kHID * kD;

    const int tid = threadIdx.x;
    const int warp = tid >> 5;
    const int lane = tid & 31;
    const int gid = lane >> 2;
    const int tig = lane & 3;
    const int wm = (warp >> 2) * 64;
    const int wn = (warp & 3) * 32;
    const int bn = blockIdx.x * 128;

    const int ar = tid >> 1;
    const int ac = (tid & 1) * 8;
    const int slot = slot0 + ar;
    const bool valid = slot < cnt;
    const int tok = valid ? g_list[e * kS + slot] : 0;
    const float wt = valid ? g_wts[e * kS + slot] : 0.f;
    const float* Ap = Hm + (size_t)tok * kHID + ac;

    const int bk0 = tid >> 5;
    const int bn4 = lane * 4;
    const float* Bp = B + (size_t)bk0 * kD + bn + bn4;

    float acc[4][4][4];
#pragma unroll
    for (int mt = 0; mt < 4; mt++)
#pragma unroll
        for (int nt = 0; nt < 4; nt++)
#pragma unroll
            for (int i = 0; i < 4; i++) acc[mt][nt][i] = 0.f;

    {
        float4 pa0 = *(const float4*)Ap;
        float4 pa1 = *(const float4*)(Ap + 4);
        float4 pb0 = *(const float4*)Bp;
        float4 pb1 = *(const float4*)(Bp + (size_t)8 * kD);
        As[0][ac + 0][ar] = f2tf32(pa0.x * wt); As[0][ac + 1][ar] = f2tf32(pa0.y * wt);
        As[0][ac + 2][ar] = f2tf32(pa0.z * wt); As[0][ac + 3][ar] = f2tf32(pa0.w * wt);
        As[0][ac + 4][ar] = f2tf32(pa1.x * wt); As[0][ac + 5][ar] = f2tf32(pa1.y * wt);
        As[0][ac + 6][ar] = f2tf32(pa1.z * wt); As[0][ac + 7][ar] = f2tf32(pa1.w * wt);
        *(uint4*)&Bs[0][bk0][bn4] =
            make_uint4(f2tf32(pb0.x), f2tf32(pb0.y), f2tf32(pb0.z), f2tf32(pb0.w));
        *(uint4*)&Bs[0][bk0 + 8][bn4] =
            make_uint4(f2tf32(pb1.x), f2tf32(pb1.y), f2tf32(pb1.z), f2tf32(pb1.w));
    }
    __syncthreads();

    const int nk = kHID / 16;
    int buf = 0;
    for (int kt = 0; kt < nk; kt++) {
        float4 pa0, pa1, pb0, pb1;
        if (kt + 1 < nk) {
            pa0 = *(const float4*)(Ap + (kt + 1) * 16);
            pa1 = *(const float4*)(Ap + (kt + 1) * 16 + 4);
            pb0 = *(const float4*)(Bp + (size_t)(kt + 1) * 16 * kD);
            pb1 = *(const float4*)(Bp + (size_t)((kt + 1) * 16 + 8) * kD);
        }
#pragma unroll
        for (int ks = 0; ks < 2; ks++) {
            const int k0 = ks * 8;
            uint32_t af[4][4], bf[4][2];
#pragma unroll
            for (int mt = 0; mt < 4; mt++) {
                const int row = wm + mt * 16 + gid;
                af[mt][0] = As[buf][k0 + tig][row];
                af[mt][1] = As[buf][k0 + tig][row + 8];
                af[mt][2] = As[buf][k0 + tig + 4][row];
                af[mt][3] = As[buf][k0 + tig + 4][row + 8];
            }
#pragma unroll
            for (int nt = 0; nt < 4; nt++) {
                const int col = wn + nt * 8 + gid;
                bf[nt][0] = Bs[buf][k0 + tig][col];
                bf[nt][1] = Bs[buf][k0 + tig + 4][col];
            }
#pragma unroll
            for (int mt = 0; mt < 4; mt++)
#pragma unroll
                for (int nt = 0; nt < 4; nt++)
                    mma_tf32(acc[mt][nt], af[mt], bf[nt]);
        }
        if (kt + 1 < nk) {
            const int nb = buf ^ 1;
            As[nb][ac + 0][ar] = f2tf32(pa0.x * wt); As[nb][ac + 1][ar] = f2tf32(pa0.y * wt);
            As[nb][ac + 2][ar] = f2tf32(pa0.z * wt); As[nb][ac + 3][ar] = f2tf32(pa0.w * wt);
            As[nb][ac + 4][ar] = f2tf32(pa1.x * wt); As[nb][ac + 5][ar] = f2tf32(pa1.y * wt);
            As[nb][ac + 6][ar] = f2tf32(pa1.z * wt); As[nb][ac + 7][ar] = f2tf32(pa1.w * wt);
            *(uint4*)&Bs[nb][bk0][bn4] =
                make_uint4(f2tf32(pb0.x), f2tf32(pb0.y), f2tf32(pb0.z), f2tf32(pb0.w));
            *(uint4*)&Bs[nb][bk0 + 8][bn4] =
                make_uint4(f2tf32(pb1.x), f2tf32(pb1.y), f2tf32(pb1.z), f2tf32(pb1.w));
            __syncthreads();
            buf = nb;
        }
    }

#pragma unroll
    for (int mt = 0; mt < 4; mt++) {
        const int row = row0 + wm + mt * 16 + gid;
#pragma unroll
        for (int nt = 0; nt < 4; nt++) {
            const int col = bn + wn + nt * 8 + 2 * tig;
            *(float2*)(g_contrib + (size_t)row * kD + col) =
                make_float2(acc[mt][nt][0], acc[mt][nt][1]);
            *(float2*)(g_contrib + (size_t)(row + 8) * kD + col) =
                make_float2(acc[mt][nt][2], acc[mt][nt][3]);
        }
    }
}

// ---------------------------------------------------------------------------
// RoPE (interleaved pairs) applied in-place to q and k.
// ---------------------------------------------------------------------------
__global__ void __launch_bounds__(512) rope_kernel(float* __restrict__ q, float* __restrict__ k)
{
    const int s = blockIdx.x;
    const int j = threadIdx.x;
    const int h = j >> 5;
    const int i = j & 31;
    const int t = s & (kT - 1);
    const float inv = (float)exp(-((double)(2 * i) / (double)kDH) * 9.210340371976182736);
    const float ang = (float)t * inv;
    float sn, cs;
    sincosf(ang, &sn, &cs);
    const size_t base = (size_t)s * kD + h * kDH + 2 * i;
    float q1 = q[base], q2 = q[base + 1];
    q[base]     = q1 * cs - q2 * sn;
    q[base + 1] = q1 * sn + q2 * cs;
    float k1 = k[base], k2 = k[base + 1];
    k[base]     = k1 * cs - k2 * sn;
    k[base + 1] = k1 * sn + k2 * cs;
}

// ---------------------------------------------------------------------------
// Flash attention, fp32, 64-query tiles, DH=64, non-causal. (unchanged)
// ---------------------------------------------------------------------------
__global__ void __launch_bounds__(256) flash_kernel(
    const float* __restrict__ q, const float* __restrict__ k,
    const float* __restrict__ v, float* __restrict__ o)
{
    __shared__ float Qs[64][64];
    __shared__ float KP[64][64];
    __shared__ float Vs[64][64];
    const int qt = blockIdx.x, hh = blockIdx.y, bb = blockIdx.z;
    const int tid = threadIdx.x;
    const int tx = tid & 15, ty = tid >> 4;
    const int lr = tid >> 2;
    const int lc = (tid & 3) * 16;
    const float scale = 0.125f;

    {
        const float* qp = q + ((size_t)(bb * kT + qt * 64 + lr) * kH + hh) * kDH + lc;
#pragma unroll
        for (int c = 0; c < 4; c++) {
            float4 t4 = *(const float4*)(qp + c * 4);
            Qs[lc + c * 4 + 0][lr] = t4.x * scale;
            Qs[lc + c * 4 + 1][lr] = t4.y * scale;
            Qs[lc + c * 4 + 2][lr] = t4.z * scale;
            Qs[lc + c * 4 + 3][lr] = t4.w * scale;
        }
    }
    float m_i[4], l_i[4], O[4][4];
#pragma unroll
    for (int i = 0; i < 4; i++) {
        m_i[i] = -1e30f; l_i[i] = 0.f;
#pragma unroll
        for (int j = 0; j < 4; j++) O[i][j] = 0.f;
    }

    for (int jt = 0; jt < kT / 64; jt++) {
        __syncthreads();
        {
            const float* kp = k + ((size_t)(bb * kT + jt * 64 + lr) * kH + hh) * kDH + lc;
            const float* vp = v + ((size_t)(bb * kT + jt * 64 + lr) * kH + hh) * kDH + lc;
#pragma unroll
            for (int c = 0; c < 4; c++) {
                float4 t4 = *(const float4*)(kp + c * 4);
                KP[lc + c * 4 + 0][lr] = t4.x;
                KP[lc + c * 4 + 1][lr] = t4.y;
                KP[lc + c * 4 + 2][lr] = t4.z;
                KP[lc + c * 4 + 3][lr] = t4.w;
                float4 v4 = *(const float4*)(vp + c * 4);
                *(float4*)&Vs[lr][lc + c * 4] = v4;
            }
        }
        __syncthreads();
        float s[4][4];
#pragma unroll
        for (int i = 0; i < 4; i++)
#pragma unroll
            for (int j = 0; j < 4; j++) s[i][j] = 0.f;
#pragma unroll 8
        for (int d = 0; d < 64; d++) {
            float qa[4], kb[4];
            *(float4*)qa = *(const float4*)&Qs[d][ty * 4];
            *(float4*)kb = *(const float4*)&KP[d][tx * 4];
#pragma unroll
            for (int i = 0; i < 4; i++)
#pragma unroll
                for (int j = 0; j < 4; j++) s[i][j] = fmaf(qa[i], kb[j], s[i][j]);
        }
#pragma unroll
        for (int i = 0; i < 4; i++) {
            float mx = fmaxf(fmaxf(s[i][0], s[i][1]), fmaxf(s[i][2], s[i][3]));
            mx = fmaxf(mx, __shfl_xor_sync(0xffffffffu, mx, 1, 16));
            mx = fmaxf(mx, __shfl_xor_sync(0xffffffffu, mx, 2, 16));
            mx = fmaxf(mx, __shfl_xor_sync(0xffffffffu, mx, 4, 16));
            mx = fmaxf(mx, __shfl_xor_sync(0xffffffffu, mx, 8, 16));
            const float mnew = fmaxf(m_i[i], mx);
            const float corr = __expf(m_i[i] - mnew);
            float r = 0.f;
#pragma unroll
            for (int j = 0; j < 4; j++) {
                const float p = __expf(s[i][j] - mnew);
                s[i][j] = p; r += p;
            }
            r += __shfl_xor_sync(0xffffffffu, r, 1, 16);
            r += __shfl_xor_sync(0xffffffffu, r, 2, 16);
            r += __shfl_xor_sync(0xffffffffu, r, 4, 16);
            r += __shfl_xor_sync(0xffffffffu, r, 8, 16);
            l_i[i] = l_i[i] * corr + r;
            m_i[i] = mnew;
#pragma unroll
            for (int j = 0; j < 4; j++) O[i][j] *= corr;
        }
        __syncthreads();
#pragma unroll
        for (int i = 0; i < 4; i++)
#pragma unroll
            for (int j = 0; j < 4; j++) KP[tx * 4 + j][ty * 4 + i] = s[i][j];
        __syncthreads();
#pragma unroll 8
        for (int kk = 0; kk < 64; kk++) {
            float pr[4], vr[4];
            *(float4*)pr = *(const float4*)&KP[kk][ty * 4];
            *(float4*)vr = *(const float4*)&Vs[kk][tx * 4];
#pragma unroll
            for (int i = 0; i < 4; i++)
#pragma unroll
                for (int j = 0; j < 4; j++) O[i][j] = fmaf(pr[i], vr[j], O[i][j]);
        }
    }
#pragma unroll
    for (int i = 0; i < 4; i++) {
        const float invl = 1.f / l_i[i];
        const int row = qt * 64 + ty * 4 + i;
        float* op = o + ((size_t)(bb * kT + row) * kH + hh) * kDH + tx * 4;
        *(float4*)op = make_float4(O[i][0] * invl, O[i][1] * invl, O[i][2] * invl, O[i][3] * invl);
    }
}

// ---------------------------------------------------------------------------
// RMSNorm
// ---------------------------------------------------------------------------
__global__ void __launch_bounds__(256) rmsnorm_kernel(
    const float* __restrict__ in, const float* __restrict__ w, float* __restrict__ out)
{
    __shared__ float red[8];
    const int s = blockIdx.x;
    const int tid = threadIdx.x;
    const float* row = in + (size_t)s * kD;
    float4 v = *(const float4*)(row + tid * 4);
    float ss = v.x * v.x + v.y * v.y + v.z * v.z + v.w * v.w;
#pragma unroll
    for (int o = 16; o; o >>= 1) ss += __shfl_xor_sync(0xffffffffu, ss, o);
    if ((tid & 31) == 0) red[tid >> 5] = ss;
    __syncthreads();
    if (tid < 32) {
        float r = (tid < 8) ? red[tid] : 0.f;
#pragma unroll
        for (int o = 4; o; o >>= 1) r += __shfl_xor_sync(0xffffffffu, r, o);
        if (tid == 0) red[0] = r;
    }
    __syncthreads();
    const float sc = rsqrtf(red[0] * (1.f / (float)kD) + kEPS);
    float4 wv = *(const float4*)(w + tid * 4);
    *(float4*)(out + (size_t)s * kD + tid * 4) =
        make_float4(v.x * sc * wv.x, v.y * sc * wv.y, v.z * sc * wv.z, v.w * sc * wv.w);
}

// ---------------------------------------------------------------------------
// SwiGLU
// ---------------------------------------------------------------------------
__global__ void __launch_bounds__(256) swiglu_kernel(
    const float* __restrict__ in, float* __restrict__ out)
{
    const int idx = blockIdx.x * blockDim.x + threadIdx.x;
    const int s = idx / kHID;
    const int j = idx - s * kHID;
    const float a = in[(size_t)s * 2 * kHID + j];
    const float b = in[(size_t)s * 2 * kHID + kHID + j];
    const float sig = 1.f / (1.f + expf(-a));
    out[idx] = a * sig * b;
}

// ---------------------------------------------------------------------------
// Gating: 1 warp per token.
// ---------------------------------------------------------------------------
__global__ void __launch_bounds__(128) gate_kernel(
    const float* __restrict__ x, const float* __restrict__ Wg,
    const float* __restrict__ We, const float* __restrict__ gb,
    const float* __restrict__ eb)
{
    const int s = blockIdx.x * 4 + (threadIdx.x >> 5);
    const int lane = threadIdx.x & 31;
    const float* row = x + (size_t)s * kD;
    float ag0 = 0.f, ag1 = 0.f;
    float ae[kE] = {};
    for (int d = lane; d < kD; d += 32) {
        const float xv = row[d];
        ag0 = fmaf(xv, Wg[d * 2 + 0], ag0);
        ag1 = fmaf(xv, Wg[d * 2 + 1], ag1);
#pragma unroll
        for (int e = 0; e < kE; e++) ae[e] = fmaf(xv, We[d * 8 + e], ae[e]);
    }
#pragma unroll
    for (int o = 16; o; o >>= 1) {
        ag0 += __shfl_xor_sync(0xffffffffu, ag0, o);
        ag1 += __shfl_xor_sync(0xffffffffu, ag1, o);
#pragma unroll
        for (int e = 0; e < kE; e++) ae[e] += __shfl_xor_sync(0xffffffffu, ae[e], o);
    }
    if (lane == 0) {
        const float gl0 = ag0 + gb[0], gl1 = ag1 + gb[1];
        const int gi = (gl1 > gl0) ? 1 : 0;
        const float gprob = 1.f / (1.f + expf(gi ? (gl0 - gl1) : (gl1 - gl0)));
        const int base = gi * kEPG;
        float el[kEPG];
#pragma unroll
        for (int j = 0; j < kEPG; j++) el[j] = ae[base + j] + eb[base + j];
        float mx = el[0];
#pragma unroll
        for (int j = 1; j < kEPG; j++) mx = fmaxf(mx, el[j]);
        float ex[kEPG], ssum = 0.f;
#pragma unroll
        for (int j = 0; j < kEPG; j++) { ex[j] = expf(el[j] - mx); ssum += ex[j]; }
        float p[kEPG];
        const float inv = gprob / ssum;
#pragma unroll
        for (int j = 0; j < kEPG; j++) p[j] = ex[j] * inv;
        int i1 = 0;
#pragma unroll
        for (int j = 1; j < kEPG; j++) if (p[j] > p[i1]) i1 = j;
        int i2 = (i1 == 0) ? 1 : 0;
#pragma unroll
        for (int j = 0; j < kEPG; j++) if (j != i1 && p[j] > p[i2]) i2 = j;

        int ee = base + i1;
        int sl = atomicAdd(&g_cnt[ee], 1);
        g_list[ee * kS + sl] = s; g_wts[ee * kS + sl] = p[i1];
        g_tokE[s * 2 + 0] = ee; g_tokSlot[s * 2 + 0] = sl;
        ee = base + i2;
        sl = atomicAdd(&g_cnt[ee], 1);
        g_list[ee * kS + sl] = s; g_wts[ee * kS + sl] = p[i2];
        g_tokE[s * 2 + 1] = ee; g_tokSlot[s * 2 + 1] = sl;
    }
}

__global__ void zero_cnt_kernel()
{
    if (threadIdx.x < kE) g_cnt[threadIdx.x] = 0;
}

__global__ void offsets_kernel()
{
    if (threadIdx.x == 0 && blockIdx.x == 0) {
        int off = 0, nt = 0;
        for (int e = 0; e < kE; e++) {
            g_padoff[e] = off;
            const int c = g_cnt[e];
            const int tiles = (c + 127) >> 7;
            for (int i = 0; i < tiles; i++) {
                g_tileE[nt] = e;
                g_tileRow0[nt] = off + i * 128;
                g_tileSlot0[nt] = i * 128;
                nt++;
            }
            off += tiles * 128;
        }
        g_ntiles = nt;
    }
}

// ---------------------------------------------------------------------------
// Final: out = rmsnorm(x + shared + contrib[pos0] + contrib[pos1], norm2_w)
// ---------------------------------------------------------------------------
__global__ void __launch_bounds__(256) final_kernel(
    const float* __restrict__ x, const float* __restrict__ sh,
    const float* __restrict__ w2, float* __restrict__ out)
{
    __shared__ float red[8];
    const int s = blockIdx.x;
    const int tid = threadIdx.x;
    const int e0 = g_tokE[s * 2 + 0], sl0 = g_tokSlot[s * 2 + 0];
    const int e1 = g_tokE[s * 2 + 1], sl1 = g_tokSlot[s * 2 + 1];
    const float* c0 = g_contrib + (size_t)(g_padoff[e0] + sl0) * kD;
    const float* c1 = g_contrib + (size_t)(g_padoff[e1] + sl1) * kD;
    const int j = tid * 4;
    float4 a = *(const float4*)(x + (size_t)s * kD + j);
    float4 b = *(const float4*)(sh + (size_t)s * kD + j);
    float4 p = *(const float4*)(c0 + j);
    float4 q = *(const float4*)(c1 + j);
    float4 v = make_float4(a.x + b.x + p.x + q.x, a.y + b.y + p.y + q.y,
                           a.z + b.z + p.z + q.z, a.w + b.w + p.w + q.w);
    float ss = v.x * v.x + v.y * v.y + v.z * v.z + v.w * v.w;
#pragma unroll
    for (int o = 16; o; o >>= 1) ss += __shfl_xor_sync(0xffffffffu, ss, o);
    if ((tid & 31) == 0) red[tid >> 5] = ss;
    __syncthreads();
    if (tid < 32) {
        float r = (tid < 8) ? red[tid] : 0.f;
#pragma unroll
        for (int o = 4; o; o >>= 1) r += __shfl_xor_sync(0xffffffffu, r, o);
        if (tid == 0) red[0] = r;
    }
    __syncthreads();
    const float sc = rsqrtf(red[0] * (1.f / (float)kD) + kEPS);
    float4 wv = *(const float4*)(w2 + j);
    *(float4*)(out + (size_t)s * kD + j) =
        make_float4(v.x * sc * wv.x, v.y * sc * wv.y, v.z * sc * wv.z, v.w * sc * wv.w);
}

// ---------------------------------------------------------------------------
// Launch
// ---------------------------------------------------------------------------
extern "C" void kernel_launch(void* const* d_in, const int* in_sizes, int n_in,
                              void* d_out, int out_size)
{
    (void)in_sizes; (void)n_in; (void)out_size;
    const float* src  = (const float*)d_in[0];
    const float* Wq   = (const float*)d_in[1];
    const float* Wk_c = (const float*)d_in[2];
    const float* Wv_c = (const float*)d_in[3];
    const float* Wk   = (const float*)d_in[4];
    const float* Wv   = (const float*)d_in[5];
    const float* Wo   = (const float*)d_in[6];
    const float* Wsi  = (const float*)d_in[7];
    const float* Wso  = (const float*)d_in[8];
    const float* W1s  = (const float*)d_in[9];
    const float* W2e  = (const float*)d_in[10];
    const float* Wgg  = (const float*)d_in[11];
    const float* Weg  = (const float*)d_in[12];
    const float* gbia = (const float*)d_in[13];
    const float* ebia = (const float*)d_in[14];
    const float* n1w  = (const float*)d_in[15];
    const float* n2w  = (const float*)d_in[16];
    float* out = (float*)d_out;

    float *q, *k, *v, *kc, *vc, *attn, *pre1, *x, *ff1, *mid, *sh, *h;
    cudaGetSymbolAddress((void**)&q, g_q);
    cudaGetSymbolAddress((void**)&k, g_k);
    cudaGetSymbolAddress((void**)&v, g_v);
    cudaGetSymbolAddress((void**)&kc, g_kc);
    cudaGetSymbolAddress((void**)&vc, g_vc);
    cudaGetSymbolAddress((void**)&attn, g_attn);
    cudaGetSymbolAddress((void**)&pre1, g_pre1);
    cudaGetSymbolAddress((void**)&x, g_x);
    cudaGetSymbolAddress((void**)&ff1, g_ff1);
    cudaGetSymbolAddress((void**)&mid, g_mid);
    cudaGetSymbolAddress((void**)&sh, g_sh);
    cudaGetSymbolAddress((void**)&h, g_h);

    const dim3 gDD(kD / 128, kS / 128);             // (8, 32)
    const dim3 gDC(kDC / 128, kS / 128);            // (2, 32)
    const dim3 gFF(2 * kHID / 128, kS / 128);       // (32, 32)

    // Attention projections (low-rank k/v) — tf32 tensor cores
    tgemm_kernel<0><<<gDD, 256>>>(src, Wq, q, nullptr, kS, kD, kD);
    tgemm_kernel<0><<<gDC, 256>>>(src, Wk_c, kc, nullptr, kS, kDC, kD);
    tgemm_kernel<0><<<gDC, 256>>>(src, Wv_c, vc, nullptr, kS, kDC, kD);
    tgemm_kernel<0><<<gDD, 256>>>(kc, Wk, k, nullptr, kS, kD, kDC);
    tgemm_kernel<0><<<gDD, 256>>>(vc, Wv, v, nullptr, kS, kD, kDC);

    rope_kernel<<<kS, 512>>>(q, k);
    flash_kernel<<<dim3(kT / 64, kH, kB), 256>>>(q, k, v, attn);

    // Output projection + residual, then rmsnorm
    tgemm_kernel<1><<<gDD, 256>>>(attn, Wo, pre1, src, kS, kD, kD);
    rmsnorm_kernel<<<kS, 256>>>(pre1, n1w, x);

    // Shared FFN
    tgemm_kernel<0><<<gFF, 256>>>(x, Wsi, ff1, nullptr, kS, 2 * kHID, kD);
    swiglu_kernel<<<(kS * kHID) / 256, 256>>>(ff1, mid);
    tgemm_kernel<0><<<gDD, 256>>>(mid, Wso, sh, nullptr, kS, kD, kHID);

    // Shared expert hidden h (reuse ff1 buffer)
    tgemm_kernel<0><<<gFF, 256>>>(x, W1s, ff1, nullptr, kS, 2 * kHID, kD);
    swiglu_kernel<<<(kS * kHID) / 256, 256>>>(ff1, h);

    // Gating + grouped routed GEMM
    zero_cnt_kernel<<<1, 32>>>();
    gate_kernel<<<kS / 4, 128>>>(x, Wgg, Weg, gbia, ebia);
    offsets_kernel<<<1, 32>>>();
    moe_gemm_kernel<<<dim3(kD / 128, 72), 256>>>(h, W2e);

    // Final combine + rmsnorm
    final_kernel<<<kS, 256>>>(x, sh, n2w, out);
}

// round 5
// speedup vs baseline: 2.4506x; 2.1227x over previous
#include <cuda_runtime.h>
#include <math.h>
#include <stdint.h>

// ---------------------------------------------------------------------------
// Problem constants
// ---------------------------------------------------------------------------
namespace {
constexpr int kD   = 1024;
constexpr int kH   = 16;
constexpr int kDH  = 64;
constexpr int kDC  = 256;
constexpr int kHID = 2048;
constexpr int kG   = 2;
constexpr int kEPG = 4;
constexpr int kE   = 8;
constexpr int kB   = 2;
constexpr int kT   = 2048;
constexpr int kS   = kB * kT;           // 4096 tokens
constexpr float kEPS = 1e-6f;
constexpr int kPadRows = kS * 2 + kE * 128;
constexpr int kMaxTiles = 80;
}

// ---------------------------------------------------------------------------
// Scratch (device globals — no runtime allocation allowed)
// ---------------------------------------------------------------------------
__device__ float g_q[kS * kD];
__device__ float g_k[kS * kD];
__device__ float g_v[kS * kD];
__device__ float g_kc[kS * kDC];
__device__ float g_vc[kS * kDC];
__device__ float g_attn[kS * kD];
__device__ float g_pre1[kS * kD];
__device__ float g_x[kS * kD];
__device__ float g_ff1[kS * 2 * kHID];
__device__ float g_mid[kS * kHID];
__device__ float g_sh[kS * kD];
__device__ float g_h[kS * kHID];
__device__ float g_contrib[(size_t)kPadRows * kD];
__device__ int   g_cnt[kE];
__device__ int   g_list[kE * kS];
__device__ float g_wts[kE * kS];
__device__ int   g_tokE[kS * 2];
__device__ int   g_tokSlot[kS * 2];
__device__ int   g_padoff[kE];
__device__ int   g_tileE[kMaxTiles];
__device__ int   g_tileRow0[kMaxTiles];
__device__ int   g_tileSlot0[kMaxTiles];
__device__ int   g_ntiles;

// ---------------------------------------------------------------------------
// tf32 helpers
// ---------------------------------------------------------------------------
__device__ __forceinline__ uint32_t f2tf32(float v) {
    uint32_t u;
    asm("cvt.rna.tf32.f32 %0, %1;" : "=r"(u) : "f"(v));
    return u;
}

__device__ __forceinline__ void mma_tf32(float* c, const uint32_t* a, const uint32_t* b) {
    asm("mma.sync.aligned.m16n8k8.row.col.f32.tf32.tf32.f32 "
        "{%0,%1,%2,%3}, {%4,%5,%6,%7}, {%8,%9}, {%0,%1,%2,%3};\n"
        : "+f"(c[0]), "+f"(c[1]), "+f"(c[2]), "+f"(c[3])
        : "r"(a[0]), "r"(a[1]), "r"(a[2]), "r"(a[3]), "r"(b[0]), "r"(b[1]));
}

// ---------------------------------------------------------------------------
// tf32 tensor-core GEMM: C[M,N] = A[M,K] @ B[K,N] (+ Add if EPI==1)
// 128x128 block tile, BK=16, 256 threads, 8 warps of 64x32.
// ---------------------------------------------------------------------------
template <int EPI>
__global__ void __launch_bounds__(256) tgemm_kernel(
    const float* __restrict__ A, const float* __restrict__ B,
    float* __restrict__ C, const float* __restrict__ Add,
    int M, int N, int K)
{
    constexpr int PITCH = 136;
    __shared__ uint32_t As[2][16][PITCH];
    __shared__ uint32_t Bs[2][16][PITCH];

    const int tid = threadIdx.x;
    const int warp = tid >> 5;
    const int lane = tid & 31;
    const int gid = lane >> 2;
    const int tig = lane & 3;
    const int wm = (warp >> 2) * 64;
    const int wn = (warp & 3) * 32;
    const int bm = blockIdx.y * 128;
    const int bn = blockIdx.x * 128;

    const int ar = tid >> 1;
    const int ac = (tid & 1) * 8;
    const float* Ap = A + (size_t)(bm + ar) * K + ac;
    const int bk0 = tid >> 5;
    const int bn4 = (lane) * 4;
    const float* Bp = B + (size_t)bk0 * N + bn + bn4;

    float acc[4][4][4];
#pragma unroll
    for (int mt = 0; mt < 4; mt++)
#pragma unroll
        for (int nt = 0; nt < 4; nt++)
#pragma unroll
            for (int i = 0; i < 4; i++) acc[mt][nt][i] = 0.f;

    {
        float4 pa0 = *(const float4*)Ap;
        float4 pa1 = *(const float4*)(Ap + 4);
        float4 pb0 = *(const float4*)Bp;
        float4 pb1 = *(const float4*)(Bp + (size_t)8 * N);
        As[0][ac + 0][ar] = f2tf32(pa0.x); As[0][ac + 1][ar] = f2tf32(pa0.y);
        As[0][ac + 2][ar] = f2tf32(pa0.z); As[0][ac + 3][ar] = f2tf32(pa0.w);
        As[0][ac + 4][ar] = f2tf32(pa1.x); As[0][ac + 5][ar] = f2tf32(pa1.y);
        As[0][ac + 6][ar] = f2tf32(pa1.z); As[0][ac + 7][ar] = f2tf32(pa1.w);
        *(uint4*)&Bs[0][bk0][bn4] =
            make_uint4(f2tf32(pb0.x), f2tf32(pb0.y), f2tf32(pb0.z), f2tf32(pb0.w));
        *(uint4*)&Bs[0][bk0 + 8][bn4] =
            make_uint4(f2tf32(pb1.x), f2tf32(pb1.y), f2tf32(pb1.z), f2tf32(pb1.w));
    }
    __syncthreads();

    const int nk = K / 16;
    int buf = 0;
    for (int kt = 0; kt < nk; kt++) {
        float4 pa0, pa1, pb0, pb1;
        if (kt + 1 < nk) {
            pa0 = *(const float4*)(Ap + (kt + 1) * 16);
            pa1 = *(const float4*)(Ap + (kt + 1) * 16 + 4);
            pb0 = *(const float4*)(Bp + (size_t)(kt + 1) * 16 * N);
            pb1 = *(const float4*)(Bp + (size_t)((kt + 1) * 16 + 8) * N);
        }
#pragma unroll
        for (int ks = 0; ks < 2; ks++) {
            const int k0 = ks * 8;
            uint32_t af[4][4], bf[4][2];
#pragma unroll
            for (int mt = 0; mt < 4; mt++) {
                const int row = wm + mt * 16 + gid;
                af[mt][0] = As[buf][k0 + tig][row];
                af[mt][1] = As[buf][k0 + tig][row + 8];
                af[mt][2] = As[buf][k0 + tig + 4][row];
                af[mt][3] = As[buf][k0 + tig + 4][row + 8];
            }
#pragma unroll
            for (int nt = 0; nt < 4; nt++) {
                const int col = wn + nt * 8 + gid;
                bf[nt][0] = Bs[buf][k0 + tig][col];
                bf[nt][1] = Bs[buf][k0 + tig + 4][col];
            }
#pragma unroll
            for (int mt = 0; mt < 4; mt++)
#pragma unroll
                for (int nt = 0; nt < 4; nt++)
                    mma_tf32(acc[mt][nt], af[mt], bf[nt]);
        }
        if (kt + 1 < nk) {
            const int nb = buf ^ 1;
            As[nb][ac + 0][ar] = f2tf32(pa0.x); As[nb][ac + 1][ar] = f2tf32(pa0.y);
            As[nb][ac + 2][ar] = f2tf32(pa0.z); As[nb][ac + 3][ar] = f2tf32(pa0.w);
            As[nb][ac + 4][ar] = f2tf32(pa1.x); As[nb][ac + 5][ar] = f2tf32(pa1.y);
            As[nb][ac + 6][ar] = f2tf32(pa1.z); As[nb][ac + 7][ar] = f2tf32(pa1.w);
            *(uint4*)&Bs[nb][bk0][bn4] =
                make_uint4(f2tf32(pb0.x), f2tf32(pb0.y), f2tf32(pb0.z), f2tf32(pb0.w));
            *(uint4*)&Bs[nb][bk0 + 8][bn4] =
                make_uint4(f2tf32(pb1.x), f2tf32(pb1.y), f2tf32(pb1.z), f2tf32(pb1.w));
            __syncthreads();
            buf = nb;
        }
    }

#pragma unroll
    for (int mt = 0; mt < 4; mt++) {
        const int row = bm + wm + mt * 16 + gid;
#pragma unroll
        for (int nt = 0; nt < 4; nt++) {
            const int col = bn + wn + nt * 8 + 2 * tig;
            float2 r0 = make_float2(acc[mt][nt][0], acc[mt][nt][1]);
            float2 r1 = make_float2(acc[mt][nt][2], acc[mt][nt][3]);
            if (EPI == 1) {
                float2 a0 = *(const float2*)(Add + (size_t)row * N + col);
                float2 a1 = *(const float2*)(Add + (size_t)(row + 8) * N + col);
                r0.x += a0.x; r0.y += a0.y; r1.x += a1.x; r1.y += a1.y;
            }
            *(float2*)(C + (size_t)row * N + col) = r0;
            *(float2*)(C + (size_t)(row + 8) * N + col) = r1;
        }
    }
}

// ---------------------------------------------------------------------------
// Grouped MoE GEMM (tf32)
// ---------------------------------------------------------------------------
__global__ void __launch_bounds__(256) moe_gemm_kernel(
    const float* __restrict__ Hm, const float* __restrict__ W2)
{
    constexpr int PITCH = 136;
    __shared__ uint32_t As[2][16][PITCH];
    __shared__ uint32_t Bs[2][16][PITCH];

    const int t = blockIdx.y;
    if (t >= g_ntiles) return;
    const int e = g_tileE[t];
    const int row0 = g_tileRow0[t];
    const int slot0 = g_tileSlot0[t];
    const int cnt = g_cnt[e];
    const float* B = W2 + (size_t)e * kHID * kD;

    const int tid = threadIdx.x;
    const int warp = tid >> 5;
    const int lane = tid & 31;
    const int gid = lane >> 2;
    const int tig = lane & 3;
    const int wm = (warp >> 2) * 64;
    const int wn = (warp & 3) * 32;
    const int bn = blockIdx.x * 128;

    const int ar = tid >> 1;
    const int ac = (tid & 1) * 8;
    const int slot = slot0 + ar;
    const bool valid = slot < cnt;
    const int tok = valid ? g_list[e * kS + slot] : 0;
    const float wt = valid ? g_wts[e * kS + slot] : 0.f;
    const float* Ap = Hm + (size_t)tok * kHID + ac;

    const int bk0 = tid >> 5;
    const int bn4 = lane * 4;
    const float* Bp = B + (size_t)bk0 * kD + bn + bn4;

    float acc[4][4][4];
#pragma unroll
    for (int mt = 0; mt < 4; mt++)
#pragma unroll
        for (int nt = 0; nt < 4; nt++)
#pragma unroll
            for (int i = 0; i < 4; i++) acc[mt][nt][i] = 0.f;

    {
        float4 pa0 = *(const float4*)Ap;
        float4 pa1 = *(const float4*)(Ap + 4);
        float4 pb0 = *(const float4*)Bp;
        float4 pb1 = *(const float4*)(Bp + (size_t)8 * kD);
        As[0][ac + 0][ar] = f2tf32(pa0.x * wt); As[0][ac + 1][ar] = f2tf32(pa0.y * wt);
        As[0][ac + 2][ar] = f2tf32(pa0.z * wt); As[0][ac + 3][ar] = f2tf32(pa0.w * wt);
        As[0][ac + 4][ar] = f2tf32(pa1.x * wt); As[0][ac + 5][ar] = f2tf32(pa1.y * wt);
        As[0][ac + 6][ar] = f2tf32(pa1.z * wt); As[0][ac + 7][ar] = f2tf32(pa1.w * wt);
        *(uint4*)&Bs[0][bk0][bn4] =
            make_uint4(f2tf32(pb0.x), f2tf32(pb0.y), f2tf32(pb0.z), f2tf32(pb0.w));
        *(uint4*)&Bs[0][bk0 + 8][bn4] =
            make_uint4(f2tf32(pb1.x), f2tf32(pb1.y), f2tf32(pb1.z), f2tf32(pb1.w));
    }
    __syncthreads();

    const int nk = kHID / 16;
    int buf = 0;
    for (int kt = 0; kt < nk; kt++) {
        float4 pa0, pa1, pb0, pb1;
        if (kt + 1 < nk) {
            pa0 = *(const float4*)(Ap + (kt + 1) * 16);
            pa1 = *(const float4*)(Ap + (kt + 1) * 16 + 4);
            pb0 = *(const float4*)(Bp + (size_t)(kt + 1) * 16 * kD);
            pb1 = *(const float4*)(Bp + (size_t)((kt + 1) * 16 + 8) * kD);
        }
#pragma unroll
        for (int ks = 0; ks < 2; ks++) {
            const int k0 = ks * 8;
            uint32_t af[4][4], bf[4][2];
#pragma unroll
            for (int mt = 0; mt < 4; mt++) {
                const int row = wm + mt * 16 + gid;
                af[mt][0] = As[buf][k0 + tig][row];
                af[mt][1] = As[buf][k0 + tig][row + 8];
                af[mt][2] = As[buf][k0 + tig + 4][row];
                af[mt][3] = As[buf][k0 + tig + 4][row + 8];
            }
#pragma unroll
            for (int nt = 0; nt < 4; nt++) {
                const int col = wn + nt * 8 + gid;
                bf[nt][0] = Bs[buf][k0 + tig][col];
                bf[nt][1] = Bs[buf][k0 + tig + 4][col];
            }
#pragma unroll
            for (int mt = 0; mt < 4; mt++)
#pragma unroll
                for (int nt = 0; nt < 4; nt++)
                    mma_tf32(acc[mt][nt], af[mt], bf[nt]);
        }
        if (kt + 1 < nk) {
            const int nb = buf ^ 1;
            As[nb][ac + 0][ar] = f2tf32(pa0.x * wt); As[nb][ac + 1][ar] = f2tf32(pa0.y * wt);
            As[nb][ac + 2][ar] = f2tf32(pa0.z * wt); As[nb][ac + 3][ar] = f2tf32(pa0.w * wt);
            As[nb][ac + 4][ar] = f2tf32(pa1.x * wt); As[nb][ac + 5][ar] = f2tf32(pa1.y * wt);
            As[nb][ac + 6][ar] = f2tf32(pa1.z * wt); As[nb][ac + 7][ar] = f2tf32(pa1.w * wt);
            *(uint4*)&Bs[nb][bk0][bn4] =
                make_uint4(f2tf32(pb0.x), f2tf32(pb0.y), f2tf32(pb0.z), f2tf32(pb0.w));
            *(uint4*)&Bs[nb][bk0 + 8][bn4] =
                make_uint4(f2tf32(pb1.x), f2tf32(pb1.y), f2tf32(pb1.z), f2tf32(pb1.w));
            __syncthreads();
            buf = nb;
        }
    }

#pragma unroll
    for (int mt = 0; mt < 4; mt++) {
        const int row = row0 + wm + mt * 16 + gid;
#pragma unroll
        for (int nt = 0; nt < 4; nt++) {
            const int col = bn + wn + nt * 8 + 2 * tig;
            *(float2*)(g_contrib + (size_t)row * kD + col) =
                make_float2(acc[mt][nt][0], acc[mt][nt][1]);
            *(float2*)(g_contrib + (size_t)(row + 8) * kD + col) =
                make_float2(acc[mt][nt][2], acc[mt][nt][3]);
        }
    }
}

// ---------------------------------------------------------------------------
// RoPE (interleaved pairs) applied in-place to q and k.
// ---------------------------------------------------------------------------
__global__ void __launch_bounds__(512) rope_kernel(float* __restrict__ q, float* __restrict__ k)
{
    const int s = blockIdx.x;
    const int j = threadIdx.x;
    const int h = j >> 5;
    const int i = j & 31;
    const int t = s & (kT - 1);
    const float inv = (float)exp(-((double)(2 * i) / (double)kDH) * 9.210340371976182736);
    const float ang = (float)t * inv;
    float sn, cs;
    sincosf(ang, &sn, &cs);
    const size_t base = (size_t)s * kD + h * kDH + 2 * i;
    float q1 = q[base], q2 = q[base + 1];
    q[base]     = q1 * cs - q2 * sn;
    q[base + 1] = q1 * sn + q2 * cs;
    float k1 = k[base], k2 = k[base + 1];
    k[base]     = k1 * cs - k2 * sn;
    k[base + 1] = k1 * sn + k2 * cs;
}

// ---------------------------------------------------------------------------
// Flash attention, tf32 tensor cores. 64 q-rows per block, 4 warps (128 thr).
// grid (T/64, H, B). DH=64, non-causal, online softmax in fp32.
// smem pitches: Ks/Ps 68 (banks gid*4+tig), Vs 72 (banks tig*8+gid) — conflict-free.
// ---------------------------------------------------------------------------
__global__ void __launch_bounds__(128) flash_mma_kernel(
    const float* __restrict__ q, const float* __restrict__ k,
    const float* __restrict__ v, float* __restrict__ o)
{
    constexpr int KP = 68;   // pitch for Ks and Ps
    constexpr int VP = 72;   // pitch for Vs
    __shared__ uint32_t Ks[64 * KP];
    __shared__ uint32_t Vs[64 * VP];
    __shared__ uint32_t Ps[64 * KP];

    const int qt = blockIdx.x, hh = blockIdx.y, bb = blockIdx.z;
    const int tid = threadIdx.x;
    const int warp = tid >> 5;
    const int lane = tid & 31;
    const int gid = lane >> 2;
    const int tig = lane & 3;
    const int q0 = warp * 16;

    // Q fragments in registers (scaled by 1/sqrt(DH), tf32).
    uint32_t qf[8][4];
    {
        const int r0 = bb * kT + qt * 64 + q0;
        const float sc = 0.125f;
        const float* p0 = q + ((size_t)(r0 + gid) * kH + hh) * kDH + tig;
        const float* p1 = q + ((size_t)(r0 + gid + 8) * kH + hh) * kDH + tig;
#pragma unroll
        for (int kc = 0; kc < 8; kc++) {
            qf[kc][0] = f2tf32(p0[kc * 8] * sc);
            qf[kc][1] = f2tf32(p1[kc * 8] * sc);
            qf[kc][2] = f2tf32(p0[kc * 8 + 4] * sc);
            qf[kc][3] = f2tf32(p1[kc * 8 + 4] * sc);
        }
    }

    float O[8][4];
#pragma unroll
    for (int nt = 0; nt < 8; nt++)
#pragma unroll
        for (int i = 0; i < 4; i++) O[nt][i] = 0.f;
    float m0 = -1e30f, m1 = -1e30f, l0 = 0.f, l1 = 0.f;

    for (int jt = 0; jt < kT / 64; jt++) {
        __syncthreads();  // prior PV reads of Vs complete
        {
            // cooperative K/V tile load: 64 rows x 64 dims; 2 threads/row
            const int lr = tid >> 1;
            const int lc = (tid & 1) * 32;
            const float* kp = k + ((size_t)(bb * kT + jt * 64 + lr) * kH + hh) * kDH + lc;
            const float* vp = v + ((size_t)(bb * kT + jt * 64 + lr) * kH + hh) * kDH + lc;
#pragma unroll
            for (int c = 0; c < 8; c++) {
                float4 t4 = *(const float4*)(kp + c * 4);
                uint32_t* kd = &Ks[lr * KP + lc + c * 4];
                kd[0] = f2tf32(t4.x); kd[1] = f2tf32(t4.y);
                kd[2] = f2tf32(t4.z); kd[3] = f2tf32(t4.w);
                float4 v4 = *(const float4*)(vp + c * 4);
                uint32_t* vd = &Vs[lr * VP + lc + c * 4];
                vd[0] = f2tf32(v4.x); vd[1] = f2tf32(v4.y);
                vd[2] = f2tf32(v4.z); vd[3] = f2tf32(v4.w);
            }
        }
        __syncthreads();

        // S = Q @ K^T  (16 q-rows x 64 keys per warp)
        float S[8][4];
#pragma unroll
        for (int nt = 0; nt < 8; nt++)
#pragma unroll
            for (int i = 0; i < 4; i++) S[nt][i] = 0.f;
#pragma unroll
        for (int kc = 0; kc < 8; kc++) {
#pragma unroll
            for (int nt = 0; nt < 8; nt++) {
                uint32_t bf[2];
                bf[0] = Ks[(nt * 8 + gid) * KP + kc * 8 + tig];
                bf[1] = Ks[(nt * 8 + gid) * KP + kc * 8 + tig + 4];
                mma_tf32(S[nt], qf[kc], bf);
            }
        }

        // online softmax (rows gid and gid+8; stats reduced over lane quad)
        float rx0 = -1e30f, rx1 = -1e30f;
#pragma unroll
        for (int nt = 0; nt < 8; nt++) {
            rx0 = fmaxf(rx0, fmaxf(S[nt][0], S[nt][1]));
            rx1 = fmaxf(rx1, fmaxf(S[nt][2], S[nt][3]));
        }
        rx0 = fmaxf(rx0, __shfl_xor_sync(0xffffffffu, rx0, 1));
        rx0 = fmaxf(rx0, __shfl_xor_sync(0xffffffffu, rx0, 2));
        rx1 = fmaxf(rx1, __shfl_xor_sync(0xffffffffu, rx1, 1));
        rx1 = fmaxf(rx1, __shfl_xor_sync(0xffffffffu, rx1, 2));
        const float mn0 = fmaxf(m0, rx0);
        const float mn1 = fmaxf(m1, rx1);
        const float cr0 = __expf(m0 - mn0);
        const float cr1 = __expf(m1 - mn1);
        float rs0 = 0.f, rs1 = 0.f;
#pragma unroll
        for (int nt = 0; nt < 8; nt++) {
            S[nt][0] = __expf(S[nt][0] - mn0);
            S[nt][1] = __expf(S[nt][1] - mn0);
            S[nt][2] = __expf(S[nt][2] - mn1);
            S[nt][3] = __expf(S[nt][3] - mn1);
            rs0 += S[nt][0] + S[nt][1];
            rs1 += S[nt][2] + S[nt][3];
        }
        rs0 += __shfl_xor_sync(0xffffffffu, rs0, 1);
        rs0 += __shfl_xor_sync(0xffffffffu, rs0, 2);
        rs1 += __shfl_xor_sync(0xffffffffu, rs1, 1);
        rs1 += __shfl_xor_sync(0xffffffffu, rs1, 2);
        l0 = l0 * cr0 + rs0;
        l1 = l1 * cr1 + rs1;
        m0 = mn0; m1 = mn1;
#pragma unroll
        for (int nt = 0; nt < 8; nt++) {
            O[nt][0] *= cr0; O[nt][1] *= cr0;
            O[nt][2] *= cr1; O[nt][3] *= cr1;
        }

        // write P (tf32) to Ps — warp-private rows q0..q0+15
#pragma unroll
        for (int nt = 0; nt < 8; nt++) {
            uint32_t* r0p = &Ps[(q0 + gid) * KP + nt * 8 + 2 * tig];
            r0p[0] = f2tf32(S[nt][0]); r0p[1] = f2tf32(S[nt][1]);
            uint32_t* r1p = &Ps[(q0 + gid + 8) * KP + nt * 8 + 2 * tig];
            r1p[0] = f2tf32(S[nt][2]); r1p[1] = f2tf32(S[nt][3]);
        }
        __syncwarp();

        // O += P @ V
#pragma unroll
        for (int kc = 0; kc < 8; kc++) {
            uint32_t af[4];
            af[0] = Ps[(q0 + gid) * KP + kc * 8 + tig];
            af[1] = Ps[(q0 + gid + 8) * KP + kc * 8 + tig];
            af[2] = Ps[(q0 + gid) * KP + kc * 8 + tig + 4];
            af[3] = Ps[(q0 + gid + 8) * KP + kc * 8 + tig + 4];
#pragma unroll
            for (int nt = 0; nt < 8; nt++) {
                uint32_t bf[2];
                bf[0] = Vs[(kc * 8 + tig) * VP + nt * 8 + gid];
                bf[1] = Vs[(kc * 8 + tig + 4) * VP + nt * 8 + gid];
                mma_tf32(O[nt], af, bf);
            }
        }
    }

    // epilogue: normalize and store
    const float inv0 = 1.f / l0;
    const float inv1 = 1.f / l1;
    const int r0 = bb * kT + qt * 64 + q0;
#pragma unroll
    for (int nt = 0; nt < 8; nt++) {
        float* o0 = o + ((size_t)(r0 + gid) * kH + hh) * kDH + nt * 8 + 2 * tig;
        float* o1 = o + ((size_t)(r0 + gid + 8) * kH + hh) * kDH + nt * 8 + 2 * tig;
        *(float2*)o0 = make_float2(O[nt][0] * inv0, O[nt][1] * inv0);
        *(float2*)o1 = make_float2(O[nt][2] * inv1, O[nt][3] * inv1);
    }
}

// ---------------------------------------------------------------------------
// RMSNorm
// ---------------------------------------------------------------------------
__global__ void __launch_bounds__(256) rmsnorm_kernel(
    const float* __restrict__ in, const float* __restrict__ w, float* __restrict__ out)
{
    __shared__ float red[8];
    const int s = blockIdx.x;
    const int tid = threadIdx.x;
    const float* row = in + (size_t)s * kD;
    float4 v = *(const float4*)(row + tid * 4);
    float ss = v.x * v.x + v.y * v.y + v.z * v.z + v.w * v.w;
#pragma unroll
    for (int o = 16; o; o >>= 1) ss += __shfl_xor_sync(0xffffffffu, ss, o);
    if ((tid & 31) == 0) red[tid >> 5] = ss;
    __syncthreads();
    if (tid < 32) {
        float r = (tid < 8) ? red[tid] : 0.f;
#pragma unroll
        for (int o = 4; o; o >>= 1) r += __shfl_xor_sync(0xffffffffu, r, o);
        if (tid == 0) red[0] = r;
    }
    __syncthreads();
    const float sc = rsqrtf(red[0] * (1.f / (float)kD) + kEPS);
    float4 wv = *(const float4*)(w + tid * 4);
    *(float4*)(out + (size_t)s * kD + tid * 4) =
        make_float4(v.x * sc * wv.x, v.y * sc * wv.y, v.z * sc * wv.z, v.w * sc * wv.w);
}

// ---------------------------------------------------------------------------
// SwiGLU
// ---------------------------------------------------------------------------
__global__ void __launch_bounds__(256) swiglu_kernel(
    const float* __restrict__ in, float* __restrict__ out)
{
    const int idx = blockIdx.x * blockDim.x + threadIdx.x;
    const int s = idx / kHID;
    const int j = idx - s * kHID;
    const float a = in[(size_t)s * 2 * kHID + j];
    const float b = in[(size_t)s * 2 * kHID + kHID + j];
    const float sig = 1.f / (1.f + expf(-a));
    out[idx] = a * sig * b;
}

// ---------------------------------------------------------------------------
// Gating: 1 warp per token.
// ---------------------------------------------------------------------------
__global__ void __launch_bounds__(128) gate_kernel(
    const float* __restrict__ x, const float* __restrict__ Wg,
    const float* __restrict__ We, const float* __restrict__ gb,
    const float* __restrict__ eb)
{
    const int s = blockIdx.x * 4 + (threadIdx.x >> 5);
    const int lane = threadIdx.x & 31;
    const float* row = x + (size_t)s * kD;
    float ag0 = 0.f, ag1 = 0.f;
    float ae[kE] = {};
    for (int d = lane; d < kD; d += 32) {
        const float xv = row[d];
        ag0 = fmaf(xv, Wg[d * 2 + 0], ag0);
        ag1 = fmaf(xv, Wg[d * 2 + 1], ag1);
#pragma unroll
        for (int e = 0; e < kE; e++) ae[e] = fmaf(xv, We[d * 8 + e], ae[e]);
    }
#pragma unroll
    for (int o = 16; o; o >>= 1) {
        ag0 += __shfl_xor_sync(0xffffffffu, ag0, o);
        ag1 += __shfl_xor_sync(0xffffffffu, ag1, o);
#pragma unroll
        for (int e = 0; e < kE; e++) ae[e] += __shfl_xor_sync(0xffffffffu, ae[e], o);
    }
    if (lane == 0) {
        const float gl0 = ag0 + gb[0], gl1 = ag1 + gb[1];
        const int gi = (gl1 > gl0) ? 1 : 0;
        const float gprob = 1.f / (1.f + expf(gi ? (gl0 - gl1) : (gl1 - gl0)));
        const int base = gi * kEPG;
        float el[kEPG];
#pragma unroll
        for (int j = 0; j < kEPG; j++) el[j] = ae[base + j] + eb[base + j];
        float mx = el[0];
#pragma unroll
        for (int j = 1; j < kEPG; j++) mx = fmaxf(mx, el[j]);
        float ex[kEPG], ssum = 0.f;
#pragma unroll
        for (int j = 0; j < kEPG; j++) { ex[j] = expf(el[j] - mx); ssum += ex[j]; }
        float p[kEPG];
        const float inv = gprob / ssum;
#pragma unroll
        for (int j = 0; j < kEPG; j++) p[j] = ex[j] * inv;
        int i1 = 0;
#pragma unroll
        for (int j = 1; j < kEPG; j++) if (p[j] > p[i1]) i1 = j;
        int i2 = (i1 == 0) ? 1 : 0;
#pragma unroll
        for (int j = 0; j < kEPG; j++) if (j != i1 && p[j] > p[i2]) i2 = j;

        int ee = base + i1;
        int sl = atomicAdd(&g_cnt[ee], 1);
        g_list[ee * kS + sl] = s; g_wts[ee * kS + sl] = p[i1];
        g_tokE[s * 2 + 0] = ee; g_tokSlot[s * 2 + 0] = sl;
        ee = base + i2;
        sl = atomicAdd(&g_cnt[ee], 1);
        g_list[ee * kS + sl] = s; g_wts[ee * kS + sl] = p[i2];
        g_tokE[s * 2 + 1] = ee; g_tokSlot[s * 2 + 1] = sl;
    }
}

__global__ void zero_cnt_kernel()
{
    if (threadIdx.x < kE) g_cnt[threadIdx.x] = 0;
}

__global__ void offsets_kernel()
{
    if (threadIdx.x == 0 && blockIdx.x == 0) {
        int off = 0, nt = 0;
        for (int e = 0; e < kE; e++) {
            g_padoff[e] = off;
            const int c = g_cnt[e];
            const int tiles = (c + 127) >> 7;
            for (int i = 0; i < tiles; i++) {
                g_tileE[nt] = e;
                g_tileRow0[nt] = off + i * 128;
                g_tileSlot0[nt] = i * 128;
                nt++;
            }
            off += tiles * 128;
        }
        g_ntiles = nt;
    }
}

// ---------------------------------------------------------------------------
// Final: out = rmsnorm(x + shared + contrib[pos0] + contrib[pos1], norm2_w)
// ---------------------------------------------------------------------------
__global__ void __launch_bounds__(256) final_kernel(
    const float* __restrict__ x, const float* __restrict__ sh,
    const float* __restrict__ w2, float* __restrict__ out)
{
    __shared__ float red[8];
    const int s = blockIdx.x;
    const int tid = threadIdx.x;
    const int e0 = g_tokE[s * 2 + 0], sl0 = g_tokSlot[s * 2 + 0];
    const int e1 = g_tokE[s * 2 + 1], sl1 = g_tokSlot[s * 2 + 1];
    const float* c0 = g_contrib + (size_t)(g_padoff[e0] + sl0) * kD;
    const float* c1 = g_contrib + (size_t)(g_padoff[e1] + sl1) * kD;
    const int j = tid * 4;
    float4 a = *(const float4*)(x + (size_t)s * kD + j);
    float4 b = *(const float4*)(sh + (size_t)s * kD + j);
    float4 p = *(const float4*)(c0 + j);
    float4 q = *(const float4*)(c1 + j);
    float4 v = make_float4(a.x + b.x + p.x + q.x, a.y + b.y + p.y + q.y,
                           a.z + b.z + p.z + q.z, a.w + b.w + p.w + q.w);
    float ss = v.x * v.x + v.y * v.y + v.z * v.z + v.w * v.w;
#pragma unroll
    for (int o = 16; o; o >>= 1) ss += __shfl_xor_sync(0xffffffffu, ss, o);
    if ((tid & 31) == 0) red[tid >> 5] = ss;
    __syncthreads();
    if (tid < 32) {
        float r = (tid < 8) ? red[tid] : 0.f;
#pragma unroll
        for (int o = 4; o; o >>= 1) r += __shfl_xor_sync(0xffffffffu, r, o);
        if (tid == 0) red[0] = r;
    }
    __syncthreads();
    const float sc = rsqrtf(red[0] * (1.f / (float)kD) + kEPS);
    float4 wv = *(const float4*)(w2 + j);
    *(float4*)(out + (size_t)s * kD + j) =
        make_float4(v.x * sc * wv.x, v.y * sc * wv.y, v.z * sc * wv.z, v.w * sc * wv.w);
}

// ---------------------------------------------------------------------------
// Launch
// ---------------------------------------------------------------------------
extern "C" void kernel_launch(void* const* d_in, const int* in_sizes, int n_in,
                              void* d_out, int out_size)
{
    (void)in_sizes; (void)n_in; (void)out_size;
    const float* src  = (const float*)d_in[0];
    const float* Wq   = (const float*)d_in[1];
    const float* Wk_c = (const float*)d_in[2];
    const float* Wv_c = (const float*)d_in[3];
    const float* Wk   = (const float*)d_in[4];
    const float* Wv   = (const float*)d_in[5];
    const float* Wo   = (const float*)d_in[6];
    const float* Wsi  = (const float*)d_in[7];
    const float* Wso  = (const float*)d_in[8];
    const float* W1s  = (const float*)d_in[9];
    const float* W2e  = (const float*)d_in[10];
    const float* Wgg  = (const float*)d_in[11];
    const float* Weg  = (const float*)d_in[12];
    const float* gbia = (const float*)d_in[13];
    const float* ebia = (const float*)d_in[14];
    const float* n1w  = (const float*)d_in[15];
    const float* n2w  = (const float*)d_in[16];
    float* out = (float*)d_out;

    float *q, *k, *v, *kc, *vc, *attn, *pre1, *x, *ff1, *mid, *sh, *h;
    cudaGetSymbolAddress((void**)&q, g_q);
    cudaGetSymbolAddress((void**)&k, g_k);
    cudaGetSymbolAddress((void**)&v, g_v);
    cudaGetSymbolAddress((void**)&kc, g_kc);
    cudaGetSymbolAddress((void**)&vc, g_vc);
    cudaGetSymbolAddress((void**)&attn, g_attn);
    cudaGetSymbolAddress((void**)&pre1, g_pre1);
    cudaGetSymbolAddress((void**)&x, g_x);
    cudaGetSymbolAddress((void**)&ff1, g_ff1);
    cudaGetSymbolAddress((void**)&mid, g_mid);
    cudaGetSymbolAddress((void**)&sh, g_sh);
    cudaGetSymbolAddress((void**)&h, g_h);

    const dim3 gDD(kD / 128, kS / 128);             // (8, 32)
    const dim3 gDC(kDC / 128, kS / 128);            // (2, 32)
    const dim3 gFF(2 * kHID / 128, kS / 128);       // (32, 32)

    // Attention projections (low-rank k/v) — tf32 tensor cores
    tgemm_kernel<0><<<gDD, 256>>>(src, Wq, q, nullptr, kS, kD, kD);
    tgemm_kernel<0><<<gDC, 256>>>(src, Wk_c, kc, nullptr, kS, kDC, kD);
    tgemm_kernel<0><<<gDC, 256>>>(src, Wv_c, vc, nullptr, kS, kDC, kD);
    tgemm_kernel<0><<<gDD, 256>>>(kc, Wk, k, nullptr, kS, kD, kDC);
    tgemm_kernel<0><<<gDD, 256>>>(vc, Wv, v, nullptr, kS, kD, kDC);

    rope_kernel<<<kS, 512>>>(q, k);
    flash_mma_kernel<<<dim3(kT / 64, kH, kB), 128>>>(q, k, v, attn);

    // Output projection + residual, then rmsnorm
    tgemm_kernel<1><<<gDD, 256>>>(attn, Wo, pre1, src, kS, kD, kD);
    rmsnorm_kernel<<<kS, 256>>>(pre1, n1w, x);

    // Shared FFN
    tgemm_kernel<0><<<gFF, 256>>>(x, Wsi, ff1, nullptr, kS, 2 * kHID, kD);
    swiglu_kernel<<<(kS * kHID) / 256, 256>>>(ff1, mid);
    tgemm_kernel<0><<<gDD, 256>>>(mid, Wso, sh, nullptr, kS, kD, kHID);

    // Shared expert hidden h (reuse ff1 buffer)
    tgemm_kernel<0><<<gFF, 256>>>(x, W1s, ff1, nullptr, kS, 2 * kHID, kD);
    swiglu_kernel<<<(kS * kHID) / 256, 256>>>(ff1, h);

    // Gating + grouped routed GEMM
    zero_cnt_kernel<<<1, 32>>>();
    gate_kernel<<<kS / 4, 128>>>(x, Wgg, Weg, gbia, ebia);
    offsets_kernel<<<1, 32>>>();
    moe_gemm_kernel<<<dim3(kD / 128, 72), 256>>>(h, W2e);

    // Final combine + rmsnorm
    final_kernel<<<kS, 256>>>(x, sh, n2w, out);
}

// round 8
// speedup vs baseline: 2.8330x; 1.1560x over previous
#include <cuda_runtime.h>
#include <math.h>
#include <stdint.h>

// ---------------------------------------------------------------------------
// Problem constants
// ---------------------------------------------------------------------------
namespace {
constexpr int kD   = 1024;
constexpr int kH   = 16;
constexpr int kDH  = 64;
constexpr int kDC  = 256;
constexpr int kHID = 2048;
constexpr int kG   = 2;
constexpr int kEPG = 4;
constexpr int kE   = 8;
constexpr int kB   = 2;
constexpr int kT   = 2048;
constexpr int kS   = kB * kT;           // 4096 tokens
constexpr float kEPS = 1e-6f;
constexpr int kPadRows = kS * 2 + kE * 128;
constexpr int kMaxTiles = 80;
}

// ---------------------------------------------------------------------------
// Scratch (device globals — no runtime allocation allowed)
// ---------------------------------------------------------------------------
__device__ float g_q[kS * kD];
__device__ float g_k[kS * kD];
__device__ float g_v[kS * kD];
__device__ float g_kc[kS * kDC];
__device__ float g_vc[kS * kDC];
__device__ float g_attn[kS * kD];
__device__ float g_pre1[kS * kD];
__device__ float g_x[kS * kD];
__device__ float g_ff1[kS * 2 * kHID];
__device__ float g_mid[kS * kHID];
__device__ float g_sh[kS * kD];
__device__ float g_h[kS * kHID];
__device__ float g_contrib[(size_t)kPadRows * kD];
__device__ int   g_cnt[kE];
__device__ int   g_list[kE * kS];
__device__ float g_wts[kE * kS];
__device__ int   g_tokE[kS * 2];
__device__ int   g_tokSlot[kS * 2];
__device__ int   g_padoff[kE];
__device__ int   g_tileE[kMaxTiles];
__device__ int   g_tileRow0[kMaxTiles];
__device__ int   g_tileSlot0[kMaxTiles];
__device__ int   g_ntiles;

// ---------------------------------------------------------------------------
// helpers
// ---------------------------------------------------------------------------
__device__ __forceinline__ uint32_t f2tf32(float v) {
    uint32_t u;
    asm("cvt.rna.tf32.f32 %0, %1;" : "=r"(u) : "f"(v));
    return u;
}

__device__ __forceinline__ void mma_tf32(float* c, const uint32_t* a, const uint32_t* b) {
    asm("mma.sync.aligned.m16n8k8.row.col.f32.tf32.tf32.f32 "
        "{%0,%1,%2,%3}, {%4,%5,%6,%7}, {%8,%9}, {%0,%1,%2,%3};\n"
        : "+f"(c[0]), "+f"(c[1]), "+f"(c[2]), "+f"(c[3])
        : "r"(a[0]), "r"(a[1]), "r"(a[2]), "r"(a[3]), "r"(b[0]), "r"(b[1]));
}

__device__ __forceinline__ void cp16(uint32_t dst, const void* src) {
    asm volatile("cp.async.cg.shared.global [%0], [%1], 16;" :: "r"(dst), "l"(src));
}
#define CP_COMMIT() asm volatile("cp.async.commit_group;")
#define CP_WAIT1()  asm volatile("cp.async.wait_group 1;")

// ---------------------------------------------------------------------------
// tf32 tensor-core GEMM with cp.async 3-stage pipeline.
// C[M,N] = A[M,K] @ B[K,N] (+ Add if EPI==1)
// 128x128 block tile, BK=16, 256 threads, 8 warps of 64x32.
// A smem [128][20] (pad4), B smem [16][136] (pad8) — conflict-free frag LDS.
// Raw fp32 bits fed to mma.tf32 (HW truncation).
// ---------------------------------------------------------------------------
constexpr int PA = 20;
constexpr int PB = 136;

template <int EPI>
__global__ void __launch_bounds__(256, 2) tgemm_kernel(
    const float* __restrict__ A, const float* __restrict__ B,
    float* __restrict__ C, const float* __restrict__ Add,
    int M, int N, int K)
{
    __shared__ __align__(16) float As[3][128][PA];
    __shared__ __align__(16) float Bs[3][16][PB];

    const int tid = threadIdx.x;
    const int warp = tid >> 5;
    const int lane = tid & 31;
    const int gid = lane >> 2;
    const int tig = lane & 3;
    const int wm = (warp >> 2) * 64;
    const int wn = (warp & 3) * 32;
    const int bm = blockIdx.y * 128;
    const int bn = blockIdx.x * 128;

    // A loader: thread covers row (tid>>1), 8 floats at (tid&1)*8
    const int arow = tid >> 1;
    const int acol = (tid & 1) * 8;
    const float* Ap = A + (size_t)(bm + arow) * K + acol;
    // B loader: row tid>>4, 8 floats at (tid&15)*8
    const int brow = tid >> 4;
    const int bcol = (tid & 15) * 8;
    const float* Bp = B + (size_t)brow * N + bn + bcol;

    float acc[4][4][4];
#pragma unroll
    for (int mt = 0; mt < 4; mt++)
#pragma unroll
        for (int nt = 0; nt < 4; nt++)
#pragma unroll
            for (int i = 0; i < 4; i++) acc[mt][nt][i] = 0.f;

    const uint32_t sA = (uint32_t)__cvta_generic_to_shared(&As[0][0][0]);
    const uint32_t sB = (uint32_t)__cvta_generic_to_shared(&Bs[0][0][0]);
    const uint32_t dA = sA + (arow * PA + acol) * 4;
    const uint32_t dB = sB + (brow * PB + bcol) * 4;

    auto load_stage = [&](int st, int kt) {
        const float* a = Ap + kt * 16;
        cp16(dA + st * (128 * PA * 4), a);
        cp16(dA + st * (128 * PA * 4) + 16, a + 4);
        const float* b = Bp + (size_t)kt * 16 * N;
        cp16(dB + st * (16 * PB * 4), b);
        cp16(dB + st * (16 * PB * 4) + 16, b + 4);
    };

    const int nk = K / 16;
    load_stage(0, 0); CP_COMMIT();
    load_stage(1, 1); CP_COMMIT();

    for (int kt = 0; kt < nk; kt++) {
        CP_WAIT1();
        __syncthreads();
        const int buf = kt - (kt / 3) * 3;
#pragma unroll
        for (int ks = 0; ks < 2; ks++) {
            const int k0 = ks * 8;
            uint32_t af[4][4], bf[4][2];
#pragma unroll
            for (int mt = 0; mt < 4; mt++) {
                const int row = wm + mt * 16 + gid;
                af[mt][0] = __float_as_uint(As[buf][row][k0 + tig]);
                af[mt][1] = __float_as_uint(As[buf][row + 8][k0 + tig]);
                af[mt][2] = __float_as_uint(As[buf][row][k0 + tig + 4]);
                af[mt][3] = __float_as_uint(As[buf][row + 8][k0 + tig + 4]);
            }
#pragma unroll
            for (int nt = 0; nt < 4; nt++) {
                const int col = wn + nt * 8 + gid;
                bf[nt][0] = __float_as_uint(Bs[buf][k0 + tig][col]);
                bf[nt][1] = __float_as_uint(Bs[buf][k0 + tig + 4][col]);
            }
#pragma unroll
            for (int mt = 0; mt < 4; mt++)
#pragma unroll
                for (int nt = 0; nt < 4; nt++)
                    mma_tf32(acc[mt][nt], af[mt], bf[nt]);
        }
        const int nx = kt + 2;
        if (nx < nk) {
            const int nst = nx - (nx / 3) * 3;
            load_stage(nst, nx);
        }
        CP_COMMIT();
    }

#pragma unroll
    for (int mt = 0; mt < 4; mt++) {
        const int row = bm + wm + mt * 16 + gid;
#pragma unroll
        for (int nt = 0; nt < 4; nt++) {
            const int col = bn + wn + nt * 8 + 2 * tig;
            float2 r0 = make_float2(acc[mt][nt][0], acc[mt][nt][1]);
            float2 r1 = make_float2(acc[mt][nt][2], acc[mt][nt][3]);
            if (EPI == 1) {
                float2 a0 = *(const float2*)(Add + (size_t)row * N + col);
                float2 a1 = *(const float2*)(Add + (size_t)(row + 8) * N + col);
                r0.x += a0.x; r0.y += a0.y; r1.x += a1.x; r1.y += a1.y;
            }
            *(float2*)(C + (size_t)row * N + col) = r0;
            *(float2*)(C + (size_t)(row + 8) * N + col) = r1;
        }
    }
}

// ---------------------------------------------------------------------------
// Grouped MoE GEMM (tf32, cp.async): contrib = (h[tok] @ W2[e]) scaled by wt
// in the EPILOGUE (diag(w)·(h@W2) == row scaling of output).
// ---------------------------------------------------------------------------
__global__ void __launch_bounds__(256, 2) moe_gemm_kernel(
    const float* __restrict__ Hm, const float* __restrict__ W2)
{
    __shared__ __align__(16) float As[3][128][PA];
    __shared__ __align__(16) float Bs[3][16][PB];

    const int t = blockIdx.y;
    if (t >= g_ntiles) return;
    const int e = g_tileE[t];
    const int row0 = g_tileRow0[t];
    const int slot0 = g_tileSlot0[t];
    const int cnt = g_cnt[e];
    const float* B = W2 + (size_t)e * kHID * kD;

    const int tid = threadIdx.x;
    const int warp = tid >> 5;
    const int lane = tid & 31;
    const int gid = lane >> 2;
    const int tig = lane & 3;
    const int wm = (warp >> 2) * 64;
    const int wn = (warp & 3) * 32;
    const int bn = blockIdx.x * 128;

    const int arow = tid >> 1;
    const int acol = (tid & 1) * 8;
    const int slot = slot0 + arow;
    const int tok = (slot < cnt) ? g_list[e * kS + slot] : 0;
    const float* Ap = Hm + (size_t)tok * kHID + acol;

    const int brow = tid >> 4;
    const int bcol = (tid & 15) * 8;
    const float* Bp = B + (size_t)brow * kD + bn + bcol;

    float acc[4][4][4];
#pragma unroll
    for (int mt = 0; mt < 4; mt++)
#pragma unroll
        for (int nt = 0; nt < 4; nt++)
#pragma unroll
            for (int i = 0; i < 4; i++) acc[mt][nt][i] = 0.f;

    const uint32_t sA = (uint32_t)__cvta_generic_to_shared(&As[0][0][0]);
    const uint32_t sB = (uint32_t)__cvta_generic_to_shared(&Bs[0][0][0]);
    const uint32_t dA = sA + (arow * PA + acol) * 4;
    const uint32_t dB = sB + (brow * PB + bcol) * 4;

    auto load_stage = [&](int st, int kt) {
        const float* a = Ap + kt * 16;
        cp16(dA + st * (128 * PA * 4), a);
        cp16(dA + st * (128 * PA * 4) + 16, a + 4);
        const float* b = Bp + (size_t)kt * 16 * kD;
        cp16(dB + st * (16 * PB * 4), b);
        cp16(dB + st * (16 * PB * 4) + 16, b + 4);
    };

    const int nk = kHID / 16;
    load_stage(0, 0); CP_COMMIT();
    load_stage(1, 1); CP_COMMIT();

    for (int kt = 0; kt < nk; kt++) {
        CP_WAIT1();
        __syncthreads();
        const int buf = kt - (kt / 3) * 3;
#pragma unroll
        for (int ks = 0; ks < 2; ks++) {
            const int k0 = ks * 8;
            uint32_t af[4][4], bf[4][2];
#pragma unroll
            for (int mt = 0; mt < 4; mt++) {
                const int row = wm + mt * 16 + gid;
                af[mt][0] = __float_as_uint(As[buf][row][k0 + tig]);
                af[mt][1] = __float_as_uint(As[buf][row + 8][k0 + tig]);
                af[mt][2] = __float_as_uint(As[buf][row][k0 + tig + 4]);
                af[mt][3] = __float_as_uint(As[buf][row + 8][k0 + tig + 4]);
            }
#pragma unroll
            for (int nt = 0; nt < 4; nt++) {
                const int col = wn + nt * 8 + gid;
                bf[nt][0] = __float_as_uint(Bs[buf][k0 + tig][col]);
                bf[nt][1] = __float_as_uint(Bs[buf][k0 + tig + 4][col]);
            }
#pragma unroll
            for (int mt = 0; mt < 4; mt++)
#pragma unroll
                for (int nt = 0; nt < 4; nt++)
                    mma_tf32(acc[mt][nt], af[mt], bf[nt]);
        }
        const int nx = kt + 2;
        if (nx < nk) {
            const int nst = nx - (nx / 3) * 3;
            load_stage(nst, nx);
        }
        CP_COMMIT();
    }

#pragma unroll
    for (int mt = 0; mt < 4; mt++) {
        const int rl0 = wm + mt * 16 + gid;
        const int rl1 = rl0 + 8;
        const float w0 = (slot0 + rl0 < cnt) ? g_wts[e * kS + slot0 + rl0] : 0.f;
        const float w1 = (slot0 + rl1 < cnt) ? g_wts[e * kS + slot0 + rl1] : 0.f;
#pragma unroll
        for (int nt = 0; nt < 4; nt++) {
            const int col = bn + wn + nt * 8 + 2 * tig;
            *(float2*)(g_contrib + (size_t)(row0 + rl0) * kD + col) =
                make_float2(acc[mt][nt][0] * w0, acc[mt][nt][1] * w0);
            *(float2*)(g_contrib + (size_t)(row0 + rl1) * kD + col) =
                make_float2(acc[mt][nt][2] * w1, acc[mt][nt][3] * w1);
        }
    }
}

// ---------------------------------------------------------------------------
// RoPE (interleaved pairs) applied in-place to q and k. (float-only math)
// ---------------------------------------------------------------------------
__global__ void __launch_bounds__(512) rope_kernel(float* __restrict__ q, float* __restrict__ k)
{
    const int s = blockIdx.x;
    const int j = threadIdx.x;
    const int h = j >> 5;
    const int i = j & 31;
    const int t = s & (kT - 1);
    const float inv = expf(-((float)(2 * i) * (1.f / (float)kDH)) * 9.21034037f);
    const float ang = (float)t * inv;
    float sn, cs;
    sincosf(ang, &sn, &cs);
    const size_t base = (size_t)s * kD + h * kDH + 2 * i;
    float q1 = q[base], q2 = q[base + 1];
    q[base]     = q1 * cs - q2 * sn;
    q[base + 1] = q1 * sn + q2 * cs;
    float k1 = k[base], k2 = k[base + 1];
    k[base]     = k1 * cs - k2 * sn;
    k[base + 1] = k1 * sn + k2 * cs;
}

// ---------------------------------------------------------------------------
// Flash attention, tf32 tensor cores. 64 q-rows per block, 4 warps (128 thr).
// ---------------------------------------------------------------------------
__global__ void __launch_bounds__(128) flash_mma_kernel(
    const float* __restrict__ q, const float* __restrict__ k,
    const float* __restrict__ v, float* __restrict__ o)
{
    constexpr int KP = 68;
    constexpr int VP = 72;
    __shared__ uint32_t Ks[64 * KP];
    __shared__ uint32_t Vs[64 * VP];
    __shared__ uint32_t Ps[64 * KP];

    const int qt = blockIdx.x, hh = blockIdx.y, bb = blockIdx.z;
    const int tid = threadIdx.x;
    const int warp = tid >> 5;
    const int lane = tid & 31;
    const int gid = lane >> 2;
    const int tig = lane & 3;
    const int q0 = warp * 16;

    uint32_t qf[8][4];
    {
        const int r0 = bb * kT + qt * 64 + q0;
        const float sc = 0.125f;
        const float* p0 = q + ((size_t)(r0 + gid) * kH + hh) * kDH + tig;
        const float* p1 = q + ((size_t)(r0 + gid + 8) * kH + hh) * kDH + tig;
#pragma unroll
        for (int kc = 0; kc < 8; kc++) {
            qf[kc][0] = f2tf32(p0[kc * 8] * sc);
            qf[kc][1] = f2tf32(p1[kc * 8] * sc);
            qf[kc][2] = f2tf32(p0[kc * 8 + 4] * sc);
            qf[kc][3] = f2tf32(p1[kc * 8 + 4] * sc);
        }
    }

    float O[8][4];
#pragma unroll
    for (int nt = 0; nt < 8; nt++)
#pragma unroll
        for (int i = 0; i < 4; i++) O[nt][i] = 0.f;
    float m0 = -1e30f, m1 = -1e30f, l0 = 0.f, l1 = 0.f;

    for (int jt = 0; jt < kT / 64; jt++) {
        __syncthreads();
        {
            const int lr = tid >> 1;
            const int lc = (tid & 1) * 32;
            const float* kp = k + ((size_t)(bb * kT + jt * 64 + lr) * kH + hh) * kDH + lc;
            const float* vp = v + ((size_t)(bb * kT + jt * 64 + lr) * kH + hh) * kDH + lc;
#pragma unroll
            for (int c = 0; c < 8; c++) {
                float4 t4 = *(const float4*)(kp + c * 4);
                uint32_t* kd = &Ks[lr * KP + lc + c * 4];
                kd[0] = f2tf32(t4.x); kd[1] = f2tf32(t4.y);
                kd[2] = f2tf32(t4.z); kd[3] = f2tf32(t4.w);
                float4 v4 = *(const float4*)(vp + c * 4);
                uint32_t* vd = &Vs[lr * VP + lc + c * 4];
                vd[0] = f2tf32(v4.x); vd[1] = f2tf32(v4.y);
                vd[2] = f2tf32(v4.z); vd[3] = f2tf32(v4.w);
            }
        }
        __syncthreads();

        float S[8][4];
#pragma unroll
        for (int nt = 0; nt < 8; nt++)
#pragma unroll
            for (int i = 0; i < 4; i++) S[nt][i] = 0.f;
#pragma unroll
        for (int kc = 0; kc < 8; kc++) {
#pragma unroll
            for (int nt = 0; nt < 8; nt++) {
                uint32_t bf[2];
                bf[0] = Ks[(nt * 8 + gid) * KP + kc * 8 + tig];
                bf[1] = Ks[(nt * 8 + gid) * KP + kc * 8 + tig + 4];
                mma_tf32(S[nt], qf[kc], bf);
            }
        }

        float rx0 = -1e30f, rx1 = -1e30f;
#pragma unroll
        for (int nt = 0; nt < 8; nt++) {
            rx0 = fmaxf(rx0, fmaxf(S[nt][0], S[nt][1]));
            rx1 = fmaxf(rx1, fmaxf(S[nt][2], S[nt][3]));
        }
        rx0 = fmaxf(rx0, __shfl_xor_sync(0xffffffffu, rx0, 1));
        rx0 = fmaxf(rx0, __shfl_xor_sync(0xffffffffu, rx0, 2));
        rx1 = fmaxf(rx1, __shfl_xor_sync(0xffffffffu, rx1, 1));
        rx1 = fmaxf(rx1, __shfl_xor_sync(0xffffffffu, rx1, 2));
        const float mn0 = fmaxf(m0, rx0);
        const float mn1 = fmaxf(m1, rx1);
        const float cr0 = __expf(m0 - mn0);
        const float cr1 = __expf(m1 - mn1);
        float rs0 = 0.f, rs1 = 0.f;
#pragma unroll
        for (int nt = 0; nt < 8; nt++) {
            S[nt][0] = __expf(S[nt][0] - mn0);
            S[nt][1] = __expf(S[nt][1] - mn0);
            S[nt][2] = __expf(S[nt][2] - mn1);
            S[nt][3] = __expf(S[nt][3] - mn1);
            rs0 += S[nt][0] + S[nt][1];
            rs1 += S[nt][2] + S[nt][3];
        }
        rs0 += __shfl_xor_sync(0xffffffffu, rs0, 1);
        rs0 += __shfl_xor_sync(0xffffffffu, rs0, 2);
        rs1 += __shfl_xor_sync(0xffffffffu, rs1, 1);
        rs1 += __shfl_xor_sync(0xffffffffu, rs1, 2);
        l0 = l0 * cr0 + rs0;
        l1 = l1 * cr1 + rs1;
        m0 = mn0; m1 = mn1;
#pragma unroll
        for (int nt = 0; nt < 8; nt++) {
            O[nt][0] *= cr0; O[nt][1] *= cr0;
            O[nt][2] *= cr1; O[nt][3] *= cr1;
        }

#pragma unroll
        for (int nt = 0; nt < 8; nt++) {
            uint32_t* r0p = &Ps[(q0 + gid) * KP + nt * 8 + 2 * tig];
            r0p[0] = f2tf32(S[nt][0]); r0p[1] = f2tf32(S[nt][1]);
            uint32_t* r1p = &Ps[(q0 + gid + 8) * KP + nt * 8 + 2 * tig];
            r1p[0] = f2tf32(S[nt][2]); r1p[1] = f2tf32(S[nt][3]);
        }
        __syncwarp();

#pragma unroll
        for (int kc = 0; kc < 8; kc++) {
            uint32_t af[4];
            af[0] = Ps[(q0 + gid) * KP + kc * 8 + tig];
            af[1] = Ps[(q0 + gid + 8) * KP + kc * 8 + tig];
            af[2] = Ps[(q0 + gid) * KP + kc * 8 + tig + 4];
            af[3] = Ps[(q0 + gid + 8) * KP + kc * 8 + tig + 4];
#pragma unroll
            for (int nt = 0; nt < 8; nt++) {
                uint32_t bf[2];
                bf[0] = Vs[(kc * 8 + tig) * VP + nt * 8 + gid];
                bf[1] = Vs[(kc * 8 + tig + 4) * VP + nt * 8 + gid];
                mma_tf32(O[nt], af, bf);
            }
        }
    }

    const float inv0 = 1.f / l0;
    const float inv1 = 1.f / l1;
    const int r0 = bb * kT + qt * 64 + q0;
#pragma unroll
    for (int nt = 0; nt < 8; nt++) {
        float* o0 = o + ((size_t)(r0 + gid) * kH + hh) * kDH + nt * 8 + 2 * tig;
        float* o1 = o + ((size_t)(r0 + gid + 8) * kH + hh) * kDH + nt * 8 + 2 * tig;
        *(float2*)o0 = make_float2(O[nt][0] * inv0, O[nt][1] * inv0);
        *(float2*)o1 = make_float2(O[nt][2] * inv1, O[nt][3] * inv1);
    }
}

// ---------------------------------------------------------------------------
// RMSNorm
// ---------------------------------------------------------------------------
__global__ void __launch_bounds__(256) rmsnorm_kernel(
    const float* __restrict__ in, const float* __restrict__ w, float* __restrict__ out)
{
    __shared__ float red[8];
    const int s = blockIdx.x;
    const int tid = threadIdx.x;
    const float* row = in + (size_t)s * kD;
    float4 v = *(const float4*)(row + tid * 4);
    float ss = v.x * v.x + v.y * v.y + v.z * v.z + v.w * v.w;
#pragma unroll
    for (int o = 16; o; o >>= 1) ss += __shfl_xor_sync(0xffffffffu, ss, o);
    if ((tid & 31) == 0) red[tid >> 5] = ss;
    __syncthreads();
    if (tid < 32) {
        float r = (tid < 8) ? red[tid] : 0.f;
#pragma unroll
        for (int o = 4; o; o >>= 1) r += __shfl_xor_sync(0xffffffffu, r, o);
        if (tid == 0) red[0] = r;
    }
    __syncthreads();
    const float sc = rsqrtf(red[0] * (1.f / (float)kD) + kEPS);
    float4 wv = *(const float4*)(w + tid * 4);
    *(float4*)(out + (size_t)s * kD + tid * 4) =
        make_float4(v.x * sc * wv.x, v.y * sc * wv.y, v.z * sc * wv.z, v.w * sc * wv.w);
}

// ---------------------------------------------------------------------------
// SwiGLU
// ---------------------------------------------------------------------------
__global__ void __launch_bounds__(256) swiglu_kernel(
    const float* __restrict__ in, float* __restrict__ out)
{
    const int idx = blockIdx.x * blockDim.x + threadIdx.x;
    const int s = idx / kHID;
    const int j = idx - s * kHID;
    const float a = in[(size_t)s * 2 * kHID + j];
    const float b = in[(size_t)s * 2 * kHID + kHID + j];
    const float sig = 1.f / (1.f + expf(-a));
    out[idx] = a * sig * b;
}

// ---------------------------------------------------------------------------
// Gating: 1 warp per token.
// ---------------------------------------------------------------------------
__global__ void __launch_bounds__(128) gate_kernel(
    const float* __restrict__ x, const float* __restrict__ Wg,
    const float* __restrict__ We, const float* __restrict__ gb,
    const float* __restrict__ eb)
{
    const int s = blockIdx.x * 4 + (threadIdx.x >> 5);
    const int lane = threadIdx.x & 31;
    const float* row = x + (size_t)s * kD;
    float ag0 = 0.f, ag1 = 0.f;
    float ae[kE] = {};
    for (int d = lane; d < kD; d += 32) {
        const float xv = row[d];
        ag0 = fmaf(xv, Wg[d * 2 + 0], ag0);
        ag1 = fmaf(xv, Wg[d * 2 + 1], ag1);
#pragma unroll
        for (int e = 0; e < kE; e++) ae[e] = fmaf(xv, We[d * 8 + e], ae[e]);
    }
#pragma unroll
    for (int o = 16; o; o >>= 1) {
        ag0 += __shfl_xor_sync(0xffffffffu, ag0, o);
        ag1 += __shfl_xor_sync(0xffffffffu, ag1, o);
#pragma unroll
        for (int e = 0; e < kE; e++) ae[e] += __shfl_xor_sync(0xffffffffu, ae[e], o);
    }
    if (lane == 0) {
        const float gl0 = ag0 + gb[0], gl1 = ag1 + gb[1];
        const int gi = (gl1 > gl0) ? 1 : 0;
        const float gprob = 1.f / (1.f + expf(gi ? (gl0 - gl1) : (gl1 - gl0)));
        const int base = gi * kEPG;
        float el[kEPG];
#pragma unroll
        for (int j = 0; j < kEPG; j++) el[j] = ae[base + j] + eb[base + j];
        float mx = el[0];
#pragma unroll
        for (int j = 1; j < kEPG; j++) mx = fmaxf(mx, el[j]);
        float ex[kEPG], ssum = 0.f;
#pragma unroll
        for (int j = 0; j < kEPG; j++) { ex[j] = expf(el[j] - mx); ssum += ex[j]; }
        float p[kEPG];
        const float inv = gprob / ssum;
#pragma unroll
        for (int j = 0; j < kEPG; j++) p[j] = ex[j] * inv;
        int i1 = 0;
#pragma unroll
        for (int j = 1; j < kEPG; j++) if (p[j] > p[i1]) i1 = j;
        int i2 = (i1 == 0) ? 1 : 0;
#pragma unroll
        for (int j = 0; j < kEPG; j++) if (j != i1 && p[j] > p[i2]) i2 = j;

        int ee = base + i1;
        int sl = atomicAdd(&g_cnt[ee], 1);
        g_list[ee * kS + sl] = s; g_wts[ee * kS + sl] = p[i1];
        g_tokE[s * 2 + 0] = ee; g_tokSlot[s * 2 + 0] = sl;
        ee = base + i2;
        sl = atomicAdd(&g_cnt[ee], 1);
        g_list[ee * kS + sl] = s; g_wts[ee * kS + sl] = p[i2];
        g_tokE[s * 2 + 1] = ee; g_tokSlot[s * 2 + 1] = sl;
    }
}

__global__ void zero_cnt_kernel()
{
    if (threadIdx.x < kE) g_cnt[threadIdx.x] = 0;
}

__global__ void offsets_kernel()
{
    if (threadIdx.x == 0 && blockIdx.x == 0) {
        int off = 0, nt = 0;
        for (int e = 0; e < kE; e++) {
            g_padoff[e] = off;
            const int c = g_cnt[e];
            const int tiles = (c + 127) >> 7;
            for (int i = 0; i < tiles; i++) {
                g_tileE[nt] = e;
                g_tileRow0[nt] = off + i * 128;
                g_tileSlot0[nt] = i * 128;
                nt++;
            }
            off += tiles * 128;
        }
        g_ntiles = nt;
    }
}

// ---------------------------------------------------------------------------
// Final: out = rmsnorm(x + shared + contrib[pos0] + contrib[pos1], norm2_w)
// ---------------------------------------------------------------------------
__global__ void __launch_bounds__(256) final_kernel(
    const float* __restrict__ x, const float* __restrict__ sh,
    const float* __restrict__ w2, float* __restrict__ out)
{
    __shared__ float red[8];
    const int s = blockIdx.x;
    const int tid = threadIdx.x;
    const int e0 = g_tokE[s * 2 + 0], sl0 = g_tokSlot[s * 2 + 0];
    const int e1 = g_tokE[s * 2 + 1], sl1 = g_tokSlot[s * 2 + 1];
    const float* c0 = g_contrib + (size_t)(g_padoff[e0] + sl0) * kD;
    const float* c1 = g_contrib + (size_t)(g_padoff[e1] + sl1) * kD;
    const int j = tid * 4;
    float4 a = *(const float4*)(x + (size_t)s * kD + j);
    float4 b = *(const float4*)(sh + (size_t)s * kD + j);
    float4 p = *(const float4*)(c0 + j);
    float4 q = *(const float4*)(c1 + j);
    float4 v = make_float4(a.x + b.x + p.x + q.x, a.y + b.y + p.y + q.y,
                           a.z + b.z + p.z + q.z, a.w + b.w + p.w + q.w);
    float ss = v.x * v.x + v.y * v.y + v.z * v.z + v.w * v.w;
#pragma unroll
    for (int o = 16; o; o >>= 1) ss += __shfl_xor_sync(0xffffffffu, ss, o);
    if ((tid & 31) == 0) red[tid >> 5] = ss;
    __syncthreads();
    if (tid < 32) {
        float r = (tid < 8) ? red[tid] : 0.f;
#pragma unroll
        for (int o = 4; o; o >>= 1) r += __shfl_xor_sync(0xffffffffu, r, o);
        if (tid == 0) red[0] = r;
    }
    __syncthreads();
    const float sc = rsqrtf(red[0] * (1.f / (float)kD) + kEPS);
    float4 wv = *(const float4*)(w2 + j);
    *(float4*)(out + (size_t)s * kD + j) =
        make_float4(v.x * sc * wv.x, v.y * sc * wv.y, v.z * sc * wv.z, v.w * sc * wv.w);
}

// ---------------------------------------------------------------------------
// Launch
// ---------------------------------------------------------------------------
extern "C" void kernel_launch(void* const* d_in, const int* in_sizes, int n_in,
                              void* d_out, int out_size)
{
    (void)in_sizes; (void)n_in; (void)out_size;
    const float* src  = (const float*)d_in[0];
    const float* Wq   = (const float*)d_in[1];
    const float* Wk_c = (const float*)d_in[2];
    const float* Wv_c = (const float*)d_in[3];
    const float* Wk   = (const float*)d_in[4];
    const float* Wv   = (const float*)d_in[5];
    const float* Wo   = (const float*)d_in[6];
    const float* Wsi  = (const float*)d_in[7];
    const float* Wso  = (const float*)d_in[8];
    const float* W1s  = (const float*)d_in[9];
    const float* W2e  = (const float*)d_in[10];
    const float* Wgg  = (const float*)d_in[11];
    const float* Weg  = (const float*)d_in[12];
    const float* gbia = (const float*)d_in[13];
    const float* ebia = (const float*)d_in[14];
    const float* n1w  = (const float*)d_in[15];
    const float* n2w  = (const float*)d_in[16];
    float* out = (float*)d_out;

    float *q, *k, *v, *kc, *vc, *attn, *pre1, *x, *ff1, *mid, *sh, *h;
    cudaGetSymbolAddress((void**)&q, g_q);
    cudaGetSymbolAddress((void**)&k, g_k);
    cudaGetSymbolAddress((void**)&v, g_v);
    cudaGetSymbolAddress((void**)&kc, g_kc);
    cudaGetSymbolAddress((void**)&vc, g_vc);
    cudaGetSymbolAddress((void**)&attn, g_attn);
    cudaGetSymbolAddress((void**)&pre1, g_pre1);
    cudaGetSymbolAddress((void**)&x, g_x);
    cudaGetSymbolAddress((void**)&ff1, g_ff1);
    cudaGetSymbolAddress((void**)&mid, g_mid);
    cudaGetSymbolAddress((void**)&sh, g_sh);
    cudaGetSymbolAddress((void**)&h, g_h);

    const dim3 gDD(kD / 128, kS / 128);             // (8, 32)
    const dim3 gDC(kDC / 128, kS / 128);            // (2, 32)
    const dim3 gFF(2 * kHID / 128, kS / 128);       // (32, 32)

    // Attention projections (low-rank k/v)
    tgemm_kernel<0><<<gDD, 256>>>(src, Wq, q, nullptr, kS, kD, kD);
    tgemm_kernel<0><<<gDC, 256>>>(src, Wk_c, kc, nullptr, kS, kDC, kD);
    tgemm_kernel<0><<<gDC, 256>>>(src, Wv_c, vc, nullptr, kS, kDC, kD);
    tgemm_kernel<0><<<gDD, 256>>>(kc, Wk, k, nullptr, kS, kD, kDC);
    tgemm_kernel<0><<<gDD, 256>>>(vc, Wv, v, nullptr, kS, kD, kDC);

    rope_kernel<<<kS, 512>>>(q, k);
    flash_mma_kernel<<<dim3(kT / 64, kH, kB), 128>>>(q, k, v, attn);

    // Output projection + residual, then rmsnorm
    tgemm_kernel<1><<<gDD, 256>>>(attn, Wo, pre1, src, kS, kD, kD);
    rmsnorm_kernel<<<kS, 256>>>(pre1, n1w, x);

    // Shared FFN
    tgemm_kernel<0><<<gFF, 256>>>(x, Wsi, ff1, nullptr, kS, 2 * kHID, kD);
    swiglu_kernel<<<(kS * kHID) / 256, 256>>>(ff1, mid);
    tgemm_kernel<0><<<gDD, 256>>>(mid, Wso, sh, nullptr, kS, kD, kHID);

    // Shared expert hidden h (reuse ff1 buffer)
    tgemm_kernel<0><<<gFF, 256>>>(x, W1s, ff1, nullptr, kS, 2 * kHID, kD);
    swiglu_kernel<<<(kS * kHID) / 256, 256>>>(ff1, h);

    // Gating + grouped routed GEMM
    zero_cnt_kernel<<<1, 32>>>();
    gate_kernel<<<kS / 4, 128>>>(x, Wgg, Weg, gbia, ebia);
    offsets_kernel<<<1, 32>>>();
    moe_gemm_kernel<<<dim3(kD / 128, 72), 256>>>(h, W2e);

    // Final combine + rmsnorm
    final_kernel<<<kS, 256>>>(x, sh, n2w, out);
}

// round 9
// speedup vs baseline: 3.4183x; 1.2066x over previous
#include <cuda_runtime.h>
#include <math.h>
#include <stdint.h>

// ---------------------------------------------------------------------------
// Problem constants
// ---------------------------------------------------------------------------
namespace {
constexpr int kD   = 1024;
constexpr int kH   = 16;
constexpr int kDH  = 64;
constexpr int kDC  = 256;
constexpr int kHID = 2048;
constexpr int kG   = 2;
constexpr int kEPG = 4;
constexpr int kE   = 8;
constexpr int kB   = 2;
constexpr int kT   = 2048;
constexpr int kS   = kB * kT;           // 4096 tokens
constexpr float kEPS = 1e-6f;
constexpr int kPadRows = kS * 2 + kE * 128;
constexpr int kMaxTiles = 80;
}

// ---------------------------------------------------------------------------
// Scratch (device globals — no runtime allocation allowed)
// ---------------------------------------------------------------------------
__device__ float g_q[kS * kD];
__device__ float g_k[kS * kD];
__device__ float g_v[kS * kD];
__device__ float g_kc[kS * kDC];
__device__ float g_vc[kS * kDC];
__device__ float g_attn[kS * kD];
__device__ float g_pre1[kS * kD];
__device__ float g_x[kS * kD];
__device__ float g_ff1[kS * 2 * kHID];
__device__ float g_mid[kS * kHID];
__device__ float g_sh[kS * kD];
__device__ float g_h[kS * kHID];
__device__ float g_contrib[(size_t)kPadRows * kD];
__device__ int   g_cnt[kE];
__device__ int   g_list[kE * kS];
__device__ float g_wts[kE * kS];
__device__ int   g_tokE[kS * 2];
__device__ int   g_tokSlot[kS * 2];
__device__ int   g_padoff[kE];
__device__ int   g_tileE[kMaxTiles];
__device__ int   g_tileRow0[kMaxTiles];
__device__ int   g_tileSlot0[kMaxTiles];
__device__ int   g_ntiles;

// ---------------------------------------------------------------------------
// helpers
// ---------------------------------------------------------------------------
__device__ __forceinline__ uint32_t f2tf32(float v) {
    uint32_t u;
    asm("cvt.rna.tf32.f32 %0, %1;" : "=r"(u) : "f"(v));
    return u;
}

__device__ __forceinline__ void mma_tf32(float* c, const uint32_t* a, const uint32_t* b) {
    asm("mma.sync.aligned.m16n8k8.row.col.f32.tf32.tf32.f32 "
        "{%0,%1,%2,%3}, {%4,%5,%6,%7}, {%8,%9}, {%0,%1,%2,%3};\n"
        : "+f"(c[0]), "+f"(c[1]), "+f"(c[2]), "+f"(c[3])
        : "r"(a[0]), "r"(a[1]), "r"(a[2]), "r"(a[3]), "r"(b[0]), "r"(b[1]));
}

__device__ __forceinline__ void cp16(uint32_t dst, const void* src) {
    asm volatile("cp.async.cg.shared.global [%0], [%1], 16;" :: "r"(dst), "l"(src));
}
#define CP_COMMIT() asm volatile("cp.async.commit_group;")
#define CP_WAIT2()  asm volatile("cp.async.wait_group 2;")

// ---------------------------------------------------------------------------
// tf32 tensor-core GEMM with cp.async 4-stage pipeline (wait_group 2).
// C[M,N] = A[M,K] @ B[K,N] (+ Add if EPI==1)
// 128x128 block tile, BK=16, 256 threads, 8 warps of 64x32.
// A smem [128][20] (pad4), B smem [16][136] (pad8) — conflict-free frag LDS.
// Raw fp32 bits fed to mma.tf32 (HW truncation).
// ---------------------------------------------------------------------------
constexpr int PA = 20;
constexpr int PB = 136;

template <int EPI>
__global__ void __launch_bounds__(256, 2) tgemm_kernel(
    const float* __restrict__ A, const float* __restrict__ B,
    float* __restrict__ C, const float* __restrict__ Add,
    int M, int N, int K)
{
    __shared__ __align__(16) float As[4][128][PA];
    __shared__ __align__(16) float Bs[4][16][PB];

    const int tid = threadIdx.x;
    const int warp = tid >> 5;
    const int lane = tid & 31;
    const int gid = lane >> 2;
    const int tig = lane & 3;
    const int wm = (warp >> 2) * 64;
    const int wn = (warp & 3) * 32;
    const int bm = blockIdx.y * 128;
    const int bn = blockIdx.x * 128;

    const int arow = tid >> 1;
    const int acol = (tid & 1) * 8;
    const float* Ap = A + (size_t)(bm + arow) * K + acol;
    const int brow = tid >> 4;
    const int bcol = (tid & 15) * 8;
    const float* Bp = B + (size_t)brow * N + bn + bcol;

    float acc[4][4][4];
#pragma unroll
    for (int mt = 0; mt < 4; mt++)
#pragma unroll
        for (int nt = 0; nt < 4; nt++)
#pragma unroll
            for (int i = 0; i < 4; i++) acc[mt][nt][i] = 0.f;

    const uint32_t sA = (uint32_t)__cvta_generic_to_shared(&As[0][0][0]);
    const uint32_t sB = (uint32_t)__cvta_generic_to_shared(&Bs[0][0][0]);
    const uint32_t dA = sA + (arow * PA + acol) * 4;
    const uint32_t dB = sB + (brow * PB + bcol) * 4;

    auto load_stage = [&](int st, int kt) {
        const float* a = Ap + kt * 16;
        cp16(dA + st * (128 * PA * 4), a);
        cp16(dA + st * (128 * PA * 4) + 16, a + 4);
        const float* b = Bp + (size_t)kt * 16 * N;
        cp16(dB + st * (16 * PB * 4), b);
        cp16(dB + st * (16 * PB * 4) + 16, b + 4);
    };

    const int nk = K / 16;
    load_stage(0, 0); CP_COMMIT();
    load_stage(1, 1); CP_COMMIT();
    load_stage(2, 2); CP_COMMIT();

    for (int kt = 0; kt < nk; kt++) {
        CP_WAIT2();
        __syncthreads();
        const int buf = kt & 3;
#pragma unroll
        for (int ks = 0; ks < 2; ks++) {
            const int k0 = ks * 8;
            uint32_t af[4][4], bf[4][2];
#pragma unroll
            for (int mt = 0; mt < 4; mt++) {
                const int row = wm + mt * 16 + gid;
                af[mt][0] = __float_as_uint(As[buf][row][k0 + tig]);
                af[mt][1] = __float_as_uint(As[buf][row + 8][k0 + tig]);
                af[mt][2] = __float_as_uint(As[buf][row][k0 + tig + 4]);
                af[mt][3] = __float_as_uint(As[buf][row + 8][k0 + tig + 4]);
            }
#pragma unroll
            for (int nt = 0; nt < 4; nt++) {
                const int col = wn + nt * 8 + gid;
                bf[nt][0] = __float_as_uint(Bs[buf][k0 + tig][col]);
                bf[nt][1] = __float_as_uint(Bs[buf][k0 + tig + 4][col]);
            }
#pragma unroll
            for (int mt = 0; mt < 4; mt++)
#pragma unroll
                for (int nt = 0; nt < 4; nt++)
                    mma_tf32(acc[mt][nt], af[mt], bf[nt]);
        }
        const int nx = kt + 3;
        if (nx < nk) load_stage(nx & 3, nx);
        CP_COMMIT();
    }

#pragma unroll
    for (int mt = 0; mt < 4; mt++) {
        const int row = bm + wm + mt * 16 + gid;
#pragma unroll
        for (int nt = 0; nt < 4; nt++) {
            const int col = bn + wn + nt * 8 + 2 * tig;
            float2 r0 = make_float2(acc[mt][nt][0], acc[mt][nt][1]);
            float2 r1 = make_float2(acc[mt][nt][2], acc[mt][nt][3]);
            if (EPI == 1) {
                float2 a0 = *(const float2*)(Add + (size_t)row * N + col);
                float2 a1 = *(const float2*)(Add + (size_t)(row + 8) * N + col);
                r0.x += a0.x; r0.y += a0.y; r1.x += a1.x; r1.y += a1.y;
            }
            *(float2*)(C + (size_t)row * N + col) = r0;
            *(float2*)(C + (size_t)(row + 8) * N + col) = r1;
        }
    }
}

// ---------------------------------------------------------------------------
// Grouped MoE GEMM (tf32, cp.async 4-stage): contrib = (h[tok] @ W2[e]) * wt
// (wt applied in epilogue).
// ---------------------------------------------------------------------------
__global__ void __launch_bounds__(256, 2) moe_gemm_kernel(
    const float* __restrict__ Hm, const float* __restrict__ W2)
{
    __shared__ __align__(16) float As[4][128][PA];
    __shared__ __align__(16) float Bs[4][16][PB];

    const int t = blockIdx.y;
    if (t >= g_ntiles) return;
    const int e = g_tileE[t];
    const int row0 = g_tileRow0[t];
    const int slot0 = g_tileSlot0[t];
    const int cnt = g_cnt[e];
    const float* B = W2 + (size_t)e * kHID * kD;

    const int tid = threadIdx.x;
    const int warp = tid >> 5;
    const int lane = tid & 31;
    const int gid = lane >> 2;
    const int tig = lane & 3;
    const int wm = (warp >> 2) * 64;
    const int wn = (warp & 3) * 32;
    const int bn = blockIdx.x * 128;

    const int arow = tid >> 1;
    const int acol = (tid & 1) * 8;
    const int slot = slot0 + arow;
    const int tok = (slot < cnt) ? g_list[e * kS + slot] : 0;
    const float* Ap = Hm + (size_t)tok * kHID + acol;

    const int brow = tid >> 4;
    const int bcol = (tid & 15) * 8;
    const float* Bp = B + (size_t)brow * kD + bn + bcol;

    float acc[4][4][4];
#pragma unroll
    for (int mt = 0; mt < 4; mt++)
#pragma unroll
        for (int nt = 0; nt < 4; nt++)
#pragma unroll
            for (int i = 0; i < 4; i++) acc[mt][nt][i] = 0.f;

    const uint32_t sA = (uint32_t)__cvta_generic_to_shared(&As[0][0][0]);
    const uint32_t sB = (uint32_t)__cvta_generic_to_shared(&Bs[0][0][0]);
    const uint32_t dA = sA + (arow * PA + acol) * 4;
    const uint32_t dB = sB + (brow * PB + bcol) * 4;

    auto load_stage = [&](int st, int kt) {
        const float* a = Ap + kt * 16;
        cp16(dA + st * (128 * PA * 4), a);
        cp16(dA + st * (128 * PA * 4) + 16, a + 4);
        const float* b = Bp + (size_t)kt * 16 * kD;
        cp16(dB + st * (16 * PB * 4), b);
        cp16(dB + st * (16 * PB * 4) + 16, b + 4);
    };

    const int nk = kHID / 16;
    load_stage(0, 0); CP_COMMIT();
    load_stage(1, 1); CP_COMMIT();
    load_stage(2, 2); CP_COMMIT();

    for (int kt = 0; kt < nk; kt++) {
        CP_WAIT2();
        __syncthreads();
        const int buf = kt & 3;
#pragma unroll
        for (int ks = 0; ks < 2; ks++) {
            const int k0 = ks * 8;
            uint32_t af[4][4], bf[4][2];
#pragma unroll
            for (int mt = 0; mt < 4; mt++) {
                const int row = wm + mt * 16 + gid;
                af[mt][0] = __float_as_uint(As[buf][row][k0 + tig]);
                af[mt][1] = __float_as_uint(As[buf][row + 8][k0 + tig]);
                af[mt][2] = __float_as_uint(As[buf][row][k0 + tig + 4]);
                af[mt][3] = __float_as_uint(As[buf][row + 8][k0 + tig + 4]);
            }
#pragma unroll
            for (int nt = 0; nt < 4; nt++) {
                const int col = wn + nt * 8 + gid;
                bf[nt][0] = __float_as_uint(Bs[buf][k0 + tig][col]);
                bf[nt][1] = __float_as_uint(Bs[buf][k0 + tig + 4][col]);
            }
#pragma unroll
            for (int mt = 0; mt < 4; mt++)
#pragma unroll
                for (int nt = 0; nt < 4; nt++)
                    mma_tf32(acc[mt][nt], af[mt], bf[nt]);
        }
        const int nx = kt + 3;
        if (nx < nk) load_stage(nx & 3, nx);
        CP_COMMIT();
    }

#pragma unroll
    for (int mt = 0; mt < 4; mt++) {
        const int rl0 = wm + mt * 16 + gid;
        const int rl1 = rl0 + 8;
        const float w0 = (slot0 + rl0 < cnt) ? g_wts[e * kS + slot0 + rl0] : 0.f;
        const float w1 = (slot0 + rl1 < cnt) ? g_wts[e * kS + slot0 + rl1] : 0.f;
#pragma unroll
        for (int nt = 0; nt < 4; nt++) {
            const int col = bn + wn + nt * 8 + 2 * tig;
            *(float2*)(g_contrib + (size_t)(row0 + rl0) * kD + col) =
                make_float2(acc[mt][nt][0] * w0, acc[mt][nt][1] * w0);
            *(float2*)(g_contrib + (size_t)(row0 + rl1) * kD + col) =
                make_float2(acc[mt][nt][2] * w1, acc[mt][nt][3] * w1);
        }
    }
}

// ---------------------------------------------------------------------------
// RoPE (interleaved pairs) applied in-place to q and k.
// ---------------------------------------------------------------------------
__global__ void __launch_bounds__(512) rope_kernel(float* __restrict__ q, float* __restrict__ k)
{
    const int s = blockIdx.x;
    const int j = threadIdx.x;
    const int h = j >> 5;
    const int i = j & 31;
    const int t = s & (kT - 1);
    const float inv = expf(-((float)(2 * i) * (1.f / (float)kDH)) * 9.21034037f);
    const float ang = (float)t * inv;
    float sn, cs;
    sincosf(ang, &sn, &cs);
    const size_t base = (size_t)s * kD + h * kDH + 2 * i;
    float q1 = q[base], q2 = q[base + 1];
    q[base]     = q1 * cs - q2 * sn;
    q[base + 1] = q1 * sn + q2 * cs;
    float k1 = k[base], k2 = k[base + 1];
    k[base]     = k1 * cs - k2 * sn;
    k[base + 1] = k1 * sn + k2 * cs;
}

// ---------------------------------------------------------------------------
// Flash attention, tf32 tensor cores. 128 q-rows per block, 8 warps (256 thr).
// grid (T/128, H, B). K/V tiles shared by 8 warps -> loader cost halved/warp.
// ---------------------------------------------------------------------------
__global__ void __launch_bounds__(256) flash_mma_kernel(
    const float* __restrict__ q, const float* __restrict__ k,
    const float* __restrict__ v, float* __restrict__ o)
{
    constexpr int KP = 68;
    constexpr int VP = 72;
    __shared__ uint32_t Ks[64 * KP];    // 17408 B
    __shared__ uint32_t Vs[64 * VP];    // 18432 B
    __shared__ uint32_t Ps[128 * KP];   // 34816 B

    const int qt = blockIdx.x, hh = blockIdx.y, bb = blockIdx.z;
    const int tid = threadIdx.x;
    const int warp = tid >> 5;
    const int lane = tid & 31;
    const int gid = lane >> 2;
    const int tig = lane & 3;
    const int q0 = warp * 16;

    // Q fragments in registers (scaled by 1/sqrt(DH), tf32).
    uint32_t qf[8][4];
    {
        const int r0 = bb * kT + qt * 128 + q0;
        const float sc = 0.125f;
        const float* p0 = q + ((size_t)(r0 + gid) * kH + hh) * kDH + tig;
        const float* p1 = q + ((size_t)(r0 + gid + 8) * kH + hh) * kDH + tig;
#pragma unroll
        for (int kc = 0; kc < 8; kc++) {
            qf[kc][0] = f2tf32(p0[kc * 8] * sc);
            qf[kc][1] = f2tf32(p1[kc * 8] * sc);
            qf[kc][2] = f2tf32(p0[kc * 8 + 4] * sc);
            qf[kc][3] = f2tf32(p1[kc * 8 + 4] * sc);
        }
    }

    float O[8][4];
#pragma unroll
    for (int nt = 0; nt < 8; nt++)
#pragma unroll
        for (int i = 0; i < 4; i++) O[nt][i] = 0.f;
    float m0 = -1e30f, m1 = -1e30f, l0 = 0.f, l1 = 0.f;

    for (int jt = 0; jt < kT / 64; jt++) {
        __syncthreads();  // prior PV reads complete
        {
            // cooperative K/V tile load: 64 rows x 64 dims; 4 threads/row
            const int lr = tid >> 2;
            const int lc = (tid & 3) * 16;
            const float* kp = k + ((size_t)(bb * kT + jt * 64 + lr) * kH + hh) * kDH + lc;
            const float* vp = v + ((size_t)(bb * kT + jt * 64 + lr) * kH + hh) * kDH + lc;
#pragma unroll
            for (int c = 0; c < 4; c++) {
                float4 t4 = *(const float4*)(kp + c * 4);
                uint32_t* kd = &Ks[lr * KP + lc + c * 4];
                kd[0] = f2tf32(t4.x); kd[1] = f2tf32(t4.y);
                kd[2] = f2tf32(t4.z); kd[3] = f2tf32(t4.w);
                float4 v4 = *(const float4*)(vp + c * 4);
                uint32_t* vd = &Vs[lr * VP + lc + c * 4];
                vd[0] = f2tf32(v4.x); vd[1] = f2tf32(v4.y);
                vd[2] = f2tf32(v4.z); vd[3] = f2tf32(v4.w);
            }
        }
        __syncthreads();

        // S = Q @ K^T  (16 q-rows x 64 keys per warp)
        float S[8][4];
#pragma unroll
        for (int nt = 0; nt < 8; nt++)
#pragma unroll
            for (int i = 0; i < 4; i++) S[nt][i] = 0.f;
#pragma unroll
        for (int kc = 0; kc < 8; kc++) {
#pragma unroll
            for (int nt = 0; nt < 8; nt++) {
                uint32_t bf[2];
                bf[0] = Ks[(nt * 8 + gid) * KP + kc * 8 + tig];
                bf[1] = Ks[(nt * 8 + gid) * KP + kc * 8 + tig + 4];
                mma_tf32(S[nt], qf[kc], bf);
            }
        }

        // online softmax (rows gid and gid+8; stats reduced over lane quad)
        float rx0 = -1e30f, rx1 = -1e30f;
#pragma unroll
        for (int nt = 0; nt < 8; nt++) {
            rx0 = fmaxf(rx0, fmaxf(S[nt][0], S[nt][1]));
            rx1 = fmaxf(rx1, fmaxf(S[nt][2], S[nt][3]));
        }
        rx0 = fmaxf(rx0, __shfl_xor_sync(0xffffffffu, rx0, 1));
        rx0 = fmaxf(rx0, __shfl_xor_sync(0xffffffffu, rx0, 2));
        rx1 = fmaxf(rx1, __shfl_xor_sync(0xffffffffu, rx1, 1));
        rx1 = fmaxf(rx1, __shfl_xor_sync(0xffffffffu, rx1, 2));
        const float mn0 = fmaxf(m0, rx0);
        const float mn1 = fmaxf(m1, rx1);
        const float cr0 = __expf(m0 - mn0);
        const float cr1 = __expf(m1 - mn1);
        float rs0 = 0.f, rs1 = 0.f;
#pragma unroll
        for (int nt = 0; nt < 8; nt++) {
            S[nt][0] = __expf(S[nt][0] - mn0);
            S[nt][1] = __expf(S[nt][1] - mn0);
            S[nt][2] = __expf(S[nt][2] - mn1);
            S[nt][3] = __expf(S[nt][3] - mn1);
            rs0 += S[nt][0] + S[nt][1];
            rs1 += S[nt][2] + S[nt][3];
        }
        rs0 += __shfl_xor_sync(0xffffffffu, rs0, 1);
        rs0 += __shfl_xor_sync(0xffffffffu, rs0, 2);
        rs1 += __shfl_xor_sync(0xffffffffu, rs1, 1);
        rs1 += __shfl_xor_sync(0xffffffffu, rs1, 2);
        l0 = l0 * cr0 + rs0;
        l1 = l1 * cr1 + rs1;
        m0 = mn0; m1 = mn1;
#pragma unroll
        for (int nt = 0; nt < 8; nt++) {
            O[nt][0] *= cr0; O[nt][1] *= cr0;
            O[nt][2] *= cr1; O[nt][3] *= cr1;
        }

        // write P (tf32) to Ps — warp-private rows q0..q0+15
#pragma unroll
        for (int nt = 0; nt < 8; nt++) {
            uint32_t* r0p = &Ps[(q0 + gid) * KP + nt * 8 + 2 * tig];
            r0p[0] = f2tf32(S[nt][0]); r0p[1] = f2tf32(S[nt][1]);
            uint32_t* r1p = &Ps[(q0 + gid + 8) * KP + nt * 8 + 2 * tig];
            r1p[0] = f2tf32(S[nt][2]); r1p[1] = f2tf32(S[nt][3]);
        }
        __syncwarp();

        // O += P @ V
#pragma unroll
        for (int kc = 0; kc < 8; kc++) {
            uint32_t af[4];
            af[0] = Ps[(q0 + gid) * KP + kc * 8 + tig];
            af[1] = Ps[(q0 + gid + 8) * KP + kc * 8 + tig];
            af[2] = Ps[(q0 + gid) * KP + kc * 8 + tig + 4];
            af[3] = Ps[(q0 + gid + 8) * KP + kc * 8 + tig + 4];
#pragma unroll
            for (int nt = 0; nt < 8; nt++) {
                uint32_t bf[2];
                bf[0] = Vs[(kc * 8 + tig) * VP + nt * 8 + gid];
                bf[1] = Vs[(kc * 8 + tig + 4) * VP + nt * 8 + gid];
                mma_tf32(O[nt], af, bf);
            }
        }
    }

    // epilogue: normalize and store
    const float inv0 = 1.f / l0;
    const float inv1 = 1.f / l1;
    const int r0 = bb * kT + qt * 128 + q0;
#pragma unroll
    for (int nt = 0; nt < 8; nt++) {
        float* o0 = o + ((size_t)(r0 + gid) * kH + hh) * kDH + nt * 8 + 2 * tig;
        float* o1 = o + ((size_t)(r0 + gid + 8) * kH + hh) * kDH + nt * 8 + 2 * tig;
        *(float2*)o0 = make_float2(O[nt][0] * inv0, O[nt][1] * inv0);
        *(float2*)o1 = make_float2(O[nt][2] * inv1, O[nt][3] * inv1);
    }
}

// ---------------------------------------------------------------------------
// RMSNorm
// ---------------------------------------------------------------------------
__global__ void __launch_bounds__(256) rmsnorm_kernel(
    const float* __restrict__ in, const float* __restrict__ w, float* __restrict__ out)
{
    __shared__ float red[8];
    const int s = blockIdx.x;
    const int tid = threadIdx.x;
    const float* row = in + (size_t)s * kD;
    float4 v = *(const float4*)(row + tid * 4);
    float ss = v.x * v.x + v.y * v.y + v.z * v.z + v.w * v.w;
#pragma unroll
    for (int o = 16; o; o >>= 1) ss += __shfl_xor_sync(0xffffffffu, ss, o);
    if ((tid & 31) == 0) red[tid >> 5] = ss;
    __syncthreads();
    if (tid < 32) {
        float r = (tid < 8) ? red[tid] : 0.f;
#pragma unroll
        for (int o = 4; o; o >>= 1) r += __shfl_xor_sync(0xffffffffu, r, o);
        if (tid == 0) red[0] = r;
    }
    __syncthreads();
    const float sc = rsqrtf(red[0] * (1.f / (float)kD) + kEPS);
    float4 wv = *(const float4*)(w + tid * 4);
    *(float4*)(out + (size_t)s * kD + tid * 4) =
        make_float4(v.x * sc * wv.x, v.y * sc * wv.y, v.z * sc * wv.z, v.w * sc * wv.w);
}

// ---------------------------------------------------------------------------
// SwiGLU (float4 vectorized): out[s,j] = silu(in[s,j]) * in[s,HID+j]
// ---------------------------------------------------------------------------
__global__ void __launch_bounds__(256) swiglu_kernel(
    const float* __restrict__ in, float* __restrict__ out)
{
    const int idx4 = blockIdx.x * blockDim.x + threadIdx.x;   // over S*HID/4
    const int flat = idx4 * 4;
    const int s = flat / kHID;
    const int j = flat - s * kHID;
    float4 a = *(const float4*)(in + (size_t)s * 2 * kHID + j);
    float4 b = *(const float4*)(in + (size_t)s * 2 * kHID + kHID + j);
    float4 r;
    r.x = a.x * b.x / (1.f + __expf(-a.x));
    r.y = a.y * b.y / (1.f + __expf(-a.y));
    r.z = a.z * b.z / (1.f + __expf(-a.z));
    r.w = a.w * b.w / (1.f + __expf(-a.w));
    *(float4*)(out + (size_t)flat) = r;
}

// ---------------------------------------------------------------------------
// Gating: 1 warp per token.
// ---------------------------------------------------------------------------
__global__ void __launch_bounds__(128) gate_kernel(
    const float* __restrict__ x, const float* __restrict__ Wg,
    const float* __restrict__ We, const float* __restrict__ gb,
    const float* __restrict__ eb)
{
    const int s = blockIdx.x * 4 + (threadIdx.x >> 5);
    const int lane = threadIdx.x & 31;
    const float* row = x + (size_t)s * kD;
    float ag0 = 0.f, ag1 = 0.f;
    float ae[kE] = {};
    for (int d = lane; d < kD; d += 32) {
        const float xv = row[d];
        ag0 = fmaf(xv, Wg[d * 2 + 0], ag0);
        ag1 = fmaf(xv, Wg[d * 2 + 1], ag1);
#pragma unroll
        for (int e = 0; e < kE; e++) ae[e] = fmaf(xv, We[d * 8 + e], ae[e]);
    }
#pragma unroll
    for (int o = 16; o; o >>= 1) {
        ag0 += __shfl_xor_sync(0xffffffffu, ag0, o);
        ag1 += __shfl_xor_sync(0xffffffffu, ag1, o);
#pragma unroll
        for (int e = 0; e < kE; e++) ae[e] += __shfl_xor_sync(0xffffffffu, ae[e], o);
    }
    if (lane == 0) {
        const float gl0 = ag0 + gb[0], gl1 = ag1 + gb[1];
        const int gi = (gl1 > gl0) ? 1 : 0;
        const float gprob = 1.f / (1.f + expf(gi ? (gl0 - gl1) : (gl1 - gl0)));
        const int base = gi * kEPG;
        float el[kEPG];
#pragma unroll
        for (int j = 0; j < kEPG; j++) el[j] = ae[base + j] + eb[base + j];
        float mx = el[0];
#pragma unroll
        for (int j = 1; j < kEPG; j++) mx = fmaxf(mx, el[j]);
        float ex[kEPG], ssum = 0.f;
#pragma unroll
        for (int j = 0; j < kEPG; j++) { ex[j] = expf(el[j] - mx); ssum += ex[j]; }
        float p[kEPG];
        const float inv = gprob / ssum;
#pragma unroll
        for (int j = 0; j < kEPG; j++) p[j] = ex[j] * inv;
        int i1 = 0;
#pragma unroll
        for (int j = 1; j < kEPG; j++) if (p[j] > p[i1]) i1 = j;
        int i2 = (i1 == 0) ? 1 : 0;
#pragma unroll
        for (int j = 0; j < kEPG; j++) if (j != i1 && p[j] > p[i2]) i2 = j;

        int ee = base + i1;
        int sl = atomicAdd(&g_cnt[ee], 1);
        g_list[ee * kS + sl] = s; g_wts[ee * kS + sl] = p[i1];
        g_tokE[s * 2 + 0] = ee; g_tokSlot[s * 2 + 0] = sl;
        ee = base + i2;
        sl = atomicAdd(&g_cnt[ee], 1);
        g_list[ee * kS + sl] = s; g_wts[ee * kS + sl] = p[i2];
        g_tokE[s * 2 + 1] = ee; g_tokSlot[s * 2 + 1] = sl;
    }
}

__global__ void zero_cnt_kernel()
{
    if (threadIdx.x < kE) g_cnt[threadIdx.x] = 0;
}

__global__ void offsets_kernel()
{
    if (threadIdx.x == 0 && blockIdx.x == 0) {
        int off = 0, nt = 0;
        for (int e = 0; e < kE; e++) {
            g_padoff[e] = off;
            const int c = g_cnt[e];
            const int tiles = (c + 127) >> 7;
            for (int i = 0; i < tiles; i++) {
                g_tileE[nt] = e;
                g_tileRow0[nt] = off + i * 128;
                g_tileSlot0[nt] = i * 128;
                nt++;
            }
            off += tiles * 128;
        }
        g_ntiles = nt;
    }
}

// ---------------------------------------------------------------------------
// Final: out = rmsnorm(x + shared + contrib[pos0] + contrib[pos1], norm2_w)
// ---------------------------------------------------------------------------
__global__ void __launch_bounds__(256) final_kernel(
    const float* __restrict__ x, const float* __restrict__ sh,
    const float* __restrict__ w2, float* __restrict__ out)
{
    __shared__ float red[8];
    const int s = blockIdx.x;
    const int tid = threadIdx.x;
    const int e0 = g_tokE[s * 2 + 0], sl0 = g_tokSlot[s * 2 + 0];
    const int e1 = g_tokE[s * 2 + 1], sl1 = g_tokSlot[s * 2 + 1];
    const float* c0 = g_contrib + (size_t)(g_padoff[e0] + sl0) * kD;
    const float* c1 = g_contrib + (size_t)(g_padoff[e1] + sl1) * kD;
    const int j = tid * 4;
    float4 a = *(const float4*)(x + (size_t)s * kD + j);
    float4 b = *(const float4*)(sh + (size_t)s * kD + j);
    float4 p = *(const float4*)(c0 + j);
    float4 q = *(const float4*)(c1 + j);
    float4 v = make_float4(a.x + b.x + p.x + q.x, a.y + b.y + p.y + q.y,
                           a.z + b.z + p.z + q.z, a.w + b.w + p.w + q.w);
    float ss = v.x * v.x + v.y * v.y + v.z * v.z + v.w * v.w;
#pragma unroll
    for (int o = 16; o; o >>= 1) ss += __shfl_xor_sync(0xffffffffu, ss, o);
    if ((tid & 31) == 0) red[tid >> 5] = ss;
    __syncthreads();
    if (tid < 32) {
        float r = (tid < 8) ? red[tid] : 0.f;
#pragma unroll
        for (int o = 4; o; o >>= 1) r += __shfl_xor_sync(0xffffffffu, r, o);
        if (tid == 0) red[0] = r;
    }
    __syncthreads();
    const float sc = rsqrtf(red[0] * (1.f / (float)kD) + kEPS);
    float4 wv = *(const float4*)(w2 + j);
    *(float4*)(out + (size_t)s * kD + j) =
        make_float4(v.x * sc * wv.x, v.y * sc * wv.y, v.z * sc * wv.z, v.w * sc * wv.w);
}

// ---------------------------------------------------------------------------
// Launch
// ---------------------------------------------------------------------------
extern "C" void kernel_launch(void* const* d_in, const int* in_sizes, int n_in,
                              void* d_out, int out_size)
{
    (void)in_sizes; (void)n_in; (void)out_size;
    const float* src  = (const float*)d_in[0];
    const float* Wq   = (const float*)d_in[1];
    const float* Wk_c = (const float*)d_in[2];
    const float* Wv_c = (const float*)d_in[3];
    const float* Wk   = (const float*)d_in[4];
    const float* Wv   = (const float*)d_in[5];
    const float* Wo   = (const float*)d_in[6];
    const float* Wsi  = (const float*)d_in[7];
    const float* Wso  = (const float*)d_in[8];
    const float* W1s  = (const float*)d_in[9];
    const float* W2e  = (const float*)d_in[10];
    const float* Wgg  = (const float*)d_in[11];
    const float* Weg  = (const float*)d_in[12];
    const float* gbia = (const float*)d_in[13];
    const float* ebia = (const float*)d_in[14];
    const float* n1w  = (const float*)d_in[15];
    const float* n2w  = (const float*)d_in[16];
    float* out = (float*)d_out;

    float *q, *k, *v, *kc, *vc, *attn, *pre1, *x, *ff1, *mid, *sh, *h;
    cudaGetSymbolAddress((void**)&q, g_q);
    cudaGetSymbolAddress((void**)&k, g_k);
    cudaGetSymbolAddress((void**)&v, g_v);
    cudaGetSymbolAddress((void**)&kc, g_kc);
    cudaGetSymbolAddress((void**)&vc, g_vc);
    cudaGetSymbolAddress((void**)&attn, g_attn);
    cudaGetSymbolAddress((void**)&pre1, g_pre1);
    cudaGetSymbolAddress((void**)&x, g_x);
    cudaGetSymbolAddress((void**)&ff1, g_ff1);
    cudaGetSymbolAddress((void**)&mid, g_mid);
    cudaGetSymbolAddress((void**)&sh, g_sh);
    cudaGetSymbolAddress((void**)&h, g_h);

    const dim3 gDD(kD / 128, kS / 128);             // (8, 32)
    const dim3 gDC(kDC / 128, kS / 128);            // (2, 32)
    const dim3 gFF(2 * kHID / 128, kS / 128);       // (32, 32)

    // Attention projections (low-rank k/v)
    tgemm_kernel<0><<<gDD, 256>>>(src, Wq, q, nullptr, kS, kD, kD);
    tgemm_kernel<0><<<gDC, 256>>>(src, Wk_c, kc, nullptr, kS, kDC, kD);
    tgemm_kernel<0><<<gDC, 256>>>(src, Wv_c, vc, nullptr, kS, kDC, kD);
    tgemm_kernel<0><<<gDD, 256>>>(kc, Wk, k, nullptr, kS, kD, kDC);
    tgemm_kernel<0><<<gDD, 256>>>(vc, Wv, v, nullptr, kS, kD, kDC);

    rope_kernel<<<kS, 512>>>(q, k);
    flash_mma_kernel<<<dim3(kT / 128, kH, kB), 256>>>(q, k, v, attn);

    // Output projection + residual, then rmsnorm
    tgemm_kernel<1><<<gDD, 256>>>(attn, Wo, pre1, src, kS, kD, kD);
    rmsnorm_kernel<<<kS, 256>>>(pre1, n1w, x);

    // Shared FFN
    tgemm_kernel<0><<<gFF, 256>>>(x, Wsi, ff1, nullptr, kS, 2 * kHID, kD);
    swiglu_kernel<<<(kS * kHID / 4) / 256, 256>>>(ff1, mid);
    tgemm_kernel<0><<<gDD, 256>>>(mid, Wso, sh, nullptr, kS, kD, kHID);

    // Shared expert hidden h (reuse ff1 buffer)
    tgemm_kernel<0><<<gFF, 256>>>(x, W1s, ff1, nullptr, kS, 2 * kHID, kD);
    swiglu_kernel<<<(kS * kHID / 4) / 256, 256>>>(ff1, h);

    // Gating + grouped routed GEMM
    zero_cnt_kernel<<<1, 32>>>();
    gate_kernel<<<kS / 4, 128>>>(x, Wgg, Weg, gbia, ebia);
    offsets_kernel<<<1, 32>>>();
    moe_gemm_kernel<<<dim3(kD / 128, 72), 256>>>(h, W2e);

    // Final combine + rmsnorm
    final_kernel<<<kS, 256>>>(x, sh, n2w, out);
}